// round 4
// baseline (speedup 1.0000x reference)
#include <cuda_runtime.h>
#include <math_constants.h>

#define B_ 4
#define C_ 256
#define N_ 4096
#define CN (C_*N_)

// Scratch: q, k' (=k+pos), v in [b][c][n] layout.
static __device__ float g_q[B_*CN];
static __device__ float g_k[B_*CN];
static __device__ float g_v[B_*CN];

// ---------------------------------------------------------------------------
// Projection kernel: out[b,o,n] = sum_c W[o,c] * x[b,c,n] + bias[o] (+pos for k)
// grid: (N/64, C/64, B*3), block: 256 threads (16x16 logical), 4x4 micro-tile
// ---------------------------------------------------------------------------
__global__ __launch_bounds__(256, 1)
void proj_kernel(const float* __restrict__ x,
                 const float* __restrict__ Wq, const float* __restrict__ bq,
                 const float* __restrict__ Wk, const float* __restrict__ bk,
                 const float* __restrict__ Wv, const float* __restrict__ bv,
                 const float* __restrict__ rh, const float* __restrict__ rw)
{
    __shared__ float Ws[64][65];   // [o][kc], pad 65 to avoid bank conflicts
    __shared__ float Xs[64][64];   // [kc][n]

    const int tid = threadIdx.x;
    const int tx = tid & 15, ty = tid >> 4;
    const int n0 = blockIdx.x * 64;
    const int o0 = blockIdx.y * 64;
    const int b  = blockIdx.z / 3;
    const int p  = blockIdx.z % 3;

    const float* W    = (p == 0) ? Wq : ((p == 1) ? Wk : Wv);
    const float* bias = (p == 0) ? bq : ((p == 1) ? bk : bv);
    float* outp = ((p == 0) ? g_q : ((p == 1) ? g_k : g_v)) + b * CN;
    const float* xb = x + b * CN;

    float acc[4][4];
#pragma unroll
    for (int i = 0; i < 4; i++)
#pragma unroll
        for (int j = 0; j < 4; j++) acc[i][j] = 0.f;

    for (int c0 = 0; c0 < C_; c0 += 64) {
        for (int idx = tid; idx < 4096; idx += 256) {
            int r = idx >> 6, cc = idx & 63;
            Ws[r][cc] = W[(o0 + r) * C_ + c0 + cc];
            Xs[r][cc] = xb[(c0 + r) * N_ + n0 + cc];
        }
        __syncthreads();
#pragma unroll 4
        for (int kc = 0; kc < 64; kc++) {
            float4 xv = *(const float4*)&Xs[kc][tx * 4];
            float w0 = Ws[ty * 4 + 0][kc];
            float w1 = Ws[ty * 4 + 1][kc];
            float w2 = Ws[ty * 4 + 2][kc];
            float w3 = Ws[ty * 4 + 3][kc];
            acc[0][0] += w0 * xv.x; acc[0][1] += w0 * xv.y; acc[0][2] += w0 * xv.z; acc[0][3] += w0 * xv.w;
            acc[1][0] += w1 * xv.x; acc[1][1] += w1 * xv.y; acc[1][2] += w1 * xv.z; acc[1][3] += w1 * xv.w;
            acc[2][0] += w2 * xv.x; acc[2][1] += w2 * xv.y; acc[2][2] += w2 * xv.z; acc[2][3] += w2 * xv.w;
            acc[3][0] += w3 * xv.x; acc[3][1] += w3 * xv.y; acc[3][2] += w3 * xv.z; acc[3][3] += w3 * xv.w;
        }
        __syncthreads();
    }

    // epilogue: bias (+ positional bias for k), vectorized store
#pragma unroll
    for (int i = 0; i < 4; i++) {
        int c = o0 + ty * 4 + i;
        float bv_ = bias[c];
        float vals[4];
#pragma unroll
        for (int j = 0; j < 4; j++) {
            float t = acc[i][j] + bv_;
            if (p == 1) {
                // n = n0 + tx*4 + j; pos[c,n] = rel_h[c*64 + n/64] + rel_w[c*64 + n%64]
                t += rh[c * 64 + (n0 >> 6)] + rw[c * 64 + tx * 4 + j];
            }
            vals[j] = t;
        }
        *(float4*)&outp[c * N_ + n0 + tx * 4] = make_float4(vals[0], vals[1], vals[2], vals[3]);
    }
}

// ---------------------------------------------------------------------------
// Fused flash-attention kernel.
// grid: (N/64, B), block: 256 threads. Each block: 64 query rows, loops over
// 64-key tiles with online softmax; O accumulated in registers [4m][16c]/thread.
// smem (dynamic, floats):
//   Qt  [256][64]  @ 0       (16384)
//   Kt  [256][64]  @ 16384   (16384)
//   Vst [64][260]  @ 32768   (16640)   (V transposed: [j][c], padded)
//   Ps  [64][68]   @ 49408   (4352)    (P transposed: [j][m], padded)
//   total 53760 floats = 215040 B
//   Os  [256][68]  @ 16384 (epilogue reuse of Kt/Vst region)
// ---------------------------------------------------------------------------
__global__ __launch_bounds__(256, 1)
void attn_kernel(const float* __restrict__ x,
                 const float* __restrict__ gamma,
                 float* __restrict__ out)
{
    extern __shared__ float sm[];
    float* Qt  = sm;
    float* Kt  = sm + 16384;
    float* Vst = sm + 32768;
    float* Ps  = sm + 49408;
    float* Os  = sm + 16384;

    const int tid = threadIdx.x;
    const int tx = tid & 15, ty = tid >> 4;
    const int b  = blockIdx.y;
    const int m0 = blockIdx.x * 64;

    const float* qb = g_q + b * CN;
    const float* kb = g_k + b * CN;
    const float* vb = g_v + b * CN;

    // Load Q tile: Qt[c][r] = q[b][c][m0+r]  (contiguous copy)
    for (int idx = tid; idx < 16384; idx += 256)
        Qt[idx] = qb[(idx >> 6) * N_ + m0 + (idx & 63)];

    float oacc[4][4][4];  // [i(row)][cc(c-block)][e(c within block)]
#pragma unroll
    for (int i = 0; i < 4; i++)
#pragma unroll
        for (int cc = 0; cc < 4; cc++)
#pragma unroll
            for (int e = 0; e < 4; e++) oacc[i][cc][e] = 0.f;

    float mx[4] = {-CUDART_INF_F, -CUDART_INF_F, -CUDART_INF_F, -CUDART_INF_F};
    float l[4]  = {0.f, 0.f, 0.f, 0.f};

    for (int kt = 0; kt < 64; kt++) {
        const int k0 = kt * 64;
        __syncthreads();  // previous PV done before overwriting Kt/Vst
        for (int idx = tid; idx < 16384; idx += 256) {
            int r = idx >> 6, j = idx & 63;
            Kt[idx] = kb[r * N_ + k0 + j];
            Vst[j * 260 + r] = vb[r * N_ + k0 + j];
        }
        __syncthreads();

        // S = Q @ K'  (4x4 per thread), inner over 256 channels
        float s[4][4];
#pragma unroll
        for (int i = 0; i < 4; i++)
#pragma unroll
            for (int j = 0; j < 4; j++) s[i][j] = 0.f;

#pragma unroll 4
        for (int c = 0; c < 256; c++) {
            float4 q4 = *(const float4*)&Qt[c * 64 + ty * 4];
            float4 k4 = *(const float4*)&Kt[c * 64 + tx * 4];
            s[0][0] += q4.x * k4.x; s[0][1] += q4.x * k4.y; s[0][2] += q4.x * k4.z; s[0][3] += q4.x * k4.w;
            s[1][0] += q4.y * k4.x; s[1][1] += q4.y * k4.y; s[1][2] += q4.y * k4.z; s[1][3] += q4.y * k4.w;
            s[2][0] += q4.z * k4.x; s[2][1] += q4.z * k4.y; s[2][2] += q4.z * k4.z; s[2][3] += q4.z * k4.w;
            s[3][0] += q4.w * k4.x; s[3][1] += q4.w * k4.y; s[3][2] += q4.w * k4.z; s[3][3] += q4.w * k4.w;
        }

        // Online softmax update; each query row is spread across 16 tx lanes.
#pragma unroll
        for (int i = 0; i < 4; i++) {
            float tm = fmaxf(fmaxf(s[i][0], s[i][1]), fmaxf(s[i][2], s[i][3]));
#pragma unroll
            for (int off = 8; off > 0; off >>= 1)
                tm = fmaxf(tm, __shfl_xor_sync(0xffffffffu, tm, off));
            float nm  = fmaxf(mx[i], tm);
            float fac = __expf(mx[i] - nm);
            mx[i] = nm;
            float p0 = __expf(s[i][0] - nm);
            float p1 = __expf(s[i][1] - nm);
            float p2 = __expf(s[i][2] - nm);
            float p3 = __expf(s[i][3] - nm);
            float rs = p0 + p1 + p2 + p3;
#pragma unroll
            for (int off = 8; off > 0; off >>= 1)
                rs += __shfl_xor_sync(0xffffffffu, rs, off);
            l[i] = l[i] * fac + rs;
#pragma unroll
            for (int cc = 0; cc < 4; cc++)
#pragma unroll
                for (int e = 0; e < 4; e++) oacc[i][cc][e] *= fac;
            // P transposed: Ps[j][m]
            Ps[(tx * 4 + 0) * 68 + ty * 4 + i] = p0;
            Ps[(tx * 4 + 1) * 68 + ty * 4 + i] = p1;
            Ps[(tx * 4 + 2) * 68 + ty * 4 + i] = p2;
            Ps[(tx * 4 + 3) * 68 + ty * 4 + i] = p3;
        }
        __syncthreads();

        // O += P @ V^T : inner over 64 keys of this tile
#pragma unroll 2
        for (int j = 0; j < 64; j++) {
            float4 p4 = *(const float4*)&Ps[j * 68 + ty * 4];
            float pv[4] = {p4.x, p4.y, p4.z, p4.w};
#pragma unroll
            for (int cc = 0; cc < 4; cc++) {
                float4 v4 = *(const float4*)&Vst[j * 260 + cc * 64 + tx * 4];
                float vv[4] = {v4.x, v4.y, v4.z, v4.w};
#pragma unroll
                for (int i = 0; i < 4; i++)
#pragma unroll
                    for (int e = 0; e < 4; e++)
                        oacc[i][cc][e] += pv[i] * vv[e];
            }
        }
    }

    __syncthreads();
    // Normalize and stage O into smem as Os[c][m] for coalesced output
#pragma unroll
    for (int i = 0; i < 4; i++) {
        float inv = 1.f / l[i];
#pragma unroll
        for (int cc = 0; cc < 4; cc++)
#pragma unroll
            for (int e = 0; e < 4; e++) {
                int c = cc * 64 + tx * 4 + e;
                Os[c * 68 + ty * 4 + i] = oacc[i][cc][e] * inv;
            }
    }
    __syncthreads();

    const float gm = gamma[0];
    const float* xb = x + b * CN;
    float* ob = out + b * CN;
    for (int idx = tid; idx < 16384; idx += 256) {
        int c = idx >> 6, m = idx & 63;
        int g = c * N_ + m0 + m;
        ob[g] = gm * Os[c * 68 + m] + xb[g];
    }
}

extern "C" void kernel_launch(void* const* d_in, const int* in_sizes, int n_in,
                              void* d_out, int out_size)
{
    const float* x     = (const float*)d_in[0];
    const float* Wq    = (const float*)d_in[1];
    const float* bq    = (const float*)d_in[2];
    const float* Wk    = (const float*)d_in[3];
    const float* bk    = (const float*)d_in[4];
    const float* Wv    = (const float*)d_in[5];
    const float* bv    = (const float*)d_in[6];
    const float* rh    = (const float*)d_in[7];
    const float* rw    = (const float*)d_in[8];
    const float* gamma = (const float*)d_in[9];
    float* out = (float*)d_out;

    dim3 gp(N_ / 64, C_ / 64, B_ * 3);
    proj_kernel<<<gp, 256>>>(x, Wq, bq, Wk, bk, Wv, bv, rh, rw);

    const int smem_bytes = 53760 * (int)sizeof(float);  // 215040 B
    cudaFuncSetAttribute(attn_kernel, cudaFuncAttributeMaxDynamicSharedMemorySize, smem_bytes);
    dim3 ga(N_ / 64, B_);
    attn_kernel<<<ga, 256, smem_bytes>>>(x, gamma, out);
}

// round 5
// speedup vs baseline: 1.0012x; 1.0012x over previous
#include <cuda_runtime.h>
#include <math_constants.h>

#define B_ 4
#define C_ 256
#define N_ 4096
#define CN (C_*N_)

// Scratch: q, k' (=k+pos), v in [b][c][n] layout.
static __device__ float g_q[B_*CN];
static __device__ float g_k[B_*CN];
static __device__ float g_v[B_*CN];

// ---------------------------------------------------------------------------
// Projection kernel: out[b,o,n] = sum_c W[o,c] * x[b,c,n] + bias[o] (+pos for k)
// grid: (N/64, C/64, B*3), block: 256 threads (16x16 logical), 4x4 micro-tile
// ---------------------------------------------------------------------------
__global__ __launch_bounds__(256, 1)
void proj_kernel(const float* __restrict__ x,
                 const float* __restrict__ Wq, const float* __restrict__ bq,
                 const float* __restrict__ Wk, const float* __restrict__ bk,
                 const float* __restrict__ Wv, const float* __restrict__ bv,
                 const float* __restrict__ rh, const float* __restrict__ rw)
{
    __shared__ float Ws[64][65];   // [o][kc], pad 65 to avoid bank conflicts
    __shared__ float Xs[64][64];   // [kc][n]

    const int tid = threadIdx.x;
    const int tx = tid & 15, ty = tid >> 4;
    const int n0 = blockIdx.x * 64;
    const int o0 = blockIdx.y * 64;
    const int b  = blockIdx.z / 3;
    const int p  = blockIdx.z % 3;

    const float* W    = (p == 0) ? Wq : ((p == 1) ? Wk : Wv);
    const float* bias = (p == 0) ? bq : ((p == 1) ? bk : bv);
    float* outp = ((p == 0) ? g_q : ((p == 1) ? g_k : g_v)) + b * CN;
    const float* xb = x + b * CN;

    float acc[4][4];
#pragma unroll
    for (int i = 0; i < 4; i++)
#pragma unroll
        for (int j = 0; j < 4; j++) acc[i][j] = 0.f;

    for (int c0 = 0; c0 < C_; c0 += 64) {
        for (int idx = tid; idx < 4096; idx += 256) {
            int r = idx >> 6, cc = idx & 63;
            Ws[r][cc] = W[(o0 + r) * C_ + c0 + cc];
            Xs[r][cc] = xb[(c0 + r) * N_ + n0 + cc];
        }
        __syncthreads();
#pragma unroll 4
        for (int kc = 0; kc < 64; kc++) {
            float4 xv = *(const float4*)&Xs[kc][tx * 4];
            float w0 = Ws[ty * 4 + 0][kc];
            float w1 = Ws[ty * 4 + 1][kc];
            float w2 = Ws[ty * 4 + 2][kc];
            float w3 = Ws[ty * 4 + 3][kc];
            acc[0][0] += w0 * xv.x; acc[0][1] += w0 * xv.y; acc[0][2] += w0 * xv.z; acc[0][3] += w0 * xv.w;
            acc[1][0] += w1 * xv.x; acc[1][1] += w1 * xv.y; acc[1][2] += w1 * xv.z; acc[1][3] += w1 * xv.w;
            acc[2][0] += w2 * xv.x; acc[2][1] += w2 * xv.y; acc[2][2] += w2 * xv.z; acc[2][3] += w2 * xv.w;
            acc[3][0] += w3 * xv.x; acc[3][1] += w3 * xv.y; acc[3][2] += w3 * xv.z; acc[3][3] += w3 * xv.w;
        }
        __syncthreads();
    }

    // epilogue: bias (+ positional bias for k), vectorized store
#pragma unroll
    for (int i = 0; i < 4; i++) {
        int c = o0 + ty * 4 + i;
        float bv_ = bias[c];
        float vals[4];
#pragma unroll
        for (int j = 0; j < 4; j++) {
            float t = acc[i][j] + bv_;
            if (p == 1) {
                // n = n0 + tx*4 + j; pos[c,n] = rel_h[c*64 + n/64] + rel_w[c*64 + n%64]
                t += rh[c * 64 + (n0 >> 6)] + rw[c * 64 + tx * 4 + j];
            }
            vals[j] = t;
        }
        *(float4*)&outp[c * N_ + n0 + tx * 4] = make_float4(vals[0], vals[1], vals[2], vals[3]);
    }
}

// ---------------------------------------------------------------------------
// Fused flash-attention kernel.
// grid: (N/64, B), block: 256 threads. Each block: 64 query rows, loops over
// 64-key tiles with online softmax; O accumulated in registers [4m][16c]/thread.
// smem (dynamic, floats):
//   Qt  [256][64]  @ 0       (16384)
//   Kt  [256][64]  @ 16384   (16384)
//   Vst [64][260]  @ 32768   (16640)   (V transposed: [j][c], padded)
//   Ps  [64][68]   @ 49408   (4352)    (P transposed: [j][m], padded)
//   total 53760 floats = 215040 B
//   Os  [256][68]  @ 16384 (epilogue reuse of Kt/Vst region)
// ---------------------------------------------------------------------------
__global__ __launch_bounds__(256, 1)
void attn_kernel(const float* __restrict__ x,
                 const float* __restrict__ gamma,
                 float* __restrict__ out)
{
    extern __shared__ float sm[];
    float* Qt  = sm;
    float* Kt  = sm + 16384;
    float* Vst = sm + 32768;
    float* Ps  = sm + 49408;
    float* Os  = sm + 16384;

    const int tid = threadIdx.x;
    const int tx = tid & 15, ty = tid >> 4;
    const int b  = blockIdx.y;
    const int m0 = blockIdx.x * 64;

    const float* qb = g_q + b * CN;
    const float* kb = g_k + b * CN;
    const float* vb = g_v + b * CN;

    // Load Q tile: Qt[c][r] = q[b][c][m0+r]  (contiguous copy)
    for (int idx = tid; idx < 16384; idx += 256)
        Qt[idx] = qb[(idx >> 6) * N_ + m0 + (idx & 63)];

    float oacc[4][4][4];  // [i(row)][cc(c-block)][e(c within block)]
#pragma unroll
    for (int i = 0; i < 4; i++)
#pragma unroll
        for (int cc = 0; cc < 4; cc++)
#pragma unroll
            for (int e = 0; e < 4; e++) oacc[i][cc][e] = 0.f;

    float mx[4] = {-CUDART_INF_F, -CUDART_INF_F, -CUDART_INF_F, -CUDART_INF_F};
    float l[4]  = {0.f, 0.f, 0.f, 0.f};

    for (int kt = 0; kt < 64; kt++) {
        const int k0 = kt * 64;
        __syncthreads();  // previous PV done before overwriting Kt/Vst
        for (int idx = tid; idx < 16384; idx += 256) {
            int r = idx >> 6, j = idx & 63;
            Kt[idx] = kb[r * N_ + k0 + j];
            Vst[j * 260 + r] = vb[r * N_ + k0 + j];
        }
        __syncthreads();

        // S = Q @ K'  (4x4 per thread), inner over 256 channels
        float s[4][4];
#pragma unroll
        for (int i = 0; i < 4; i++)
#pragma unroll
            for (int j = 0; j < 4; j++) s[i][j] = 0.f;

#pragma unroll 4
        for (int c = 0; c < 256; c++) {
            float4 q4 = *(const float4*)&Qt[c * 64 + ty * 4];
            float4 k4 = *(const float4*)&Kt[c * 64 + tx * 4];
            s[0][0] += q4.x * k4.x; s[0][1] += q4.x * k4.y; s[0][2] += q4.x * k4.z; s[0][3] += q4.x * k4.w;
            s[1][0] += q4.y * k4.x; s[1][1] += q4.y * k4.y; s[1][2] += q4.y * k4.z; s[1][3] += q4.y * k4.w;
            s[2][0] += q4.z * k4.x; s[2][1] += q4.z * k4.y; s[2][2] += q4.z * k4.z; s[2][3] += q4.z * k4.w;
            s[3][0] += q4.w * k4.x; s[3][1] += q4.w * k4.y; s[3][2] += q4.w * k4.z; s[3][3] += q4.w * k4.w;
        }

        // Online softmax update; each query row is spread across 16 tx lanes.
#pragma unroll
        for (int i = 0; i < 4; i++) {
            float tm = fmaxf(fmaxf(s[i][0], s[i][1]), fmaxf(s[i][2], s[i][3]));
#pragma unroll
            for (int off = 8; off > 0; off >>= 1)
                tm = fmaxf(tm, __shfl_xor_sync(0xffffffffu, tm, off));
            float nm  = fmaxf(mx[i], tm);
            float fac = __expf(mx[i] - nm);
            mx[i] = nm;
            float p0 = __expf(s[i][0] - nm);
            float p1 = __expf(s[i][1] - nm);
            float p2 = __expf(s[i][2] - nm);
            float p3 = __expf(s[i][3] - nm);
            float rs = p0 + p1 + p2 + p3;
#pragma unroll
            for (int off = 8; off > 0; off >>= 1)
                rs += __shfl_xor_sync(0xffffffffu, rs, off);
            l[i] = l[i] * fac + rs;
#pragma unroll
            for (int cc = 0; cc < 4; cc++)
#pragma unroll
                for (int e = 0; e < 4; e++) oacc[i][cc][e] *= fac;
            // P transposed: Ps[j][m]
            Ps[(tx * 4 + 0) * 68 + ty * 4 + i] = p0;
            Ps[(tx * 4 + 1) * 68 + ty * 4 + i] = p1;
            Ps[(tx * 4 + 2) * 68 + ty * 4 + i] = p2;
            Ps[(tx * 4 + 3) * 68 + ty * 4 + i] = p3;
        }
        __syncthreads();

        // O += P @ V^T : inner over 64 keys of this tile
#pragma unroll 2
        for (int j = 0; j < 64; j++) {
            float4 p4 = *(const float4*)&Ps[j * 68 + ty * 4];
            float pv[4] = {p4.x, p4.y, p4.z, p4.w};
#pragma unroll
            for (int cc = 0; cc < 4; cc++) {
                float4 v4 = *(const float4*)&Vst[j * 260 + cc * 64 + tx * 4];
                float vv[4] = {v4.x, v4.y, v4.z, v4.w};
#pragma unroll
                for (int i = 0; i < 4; i++)
#pragma unroll
                    for (int e = 0; e < 4; e++)
                        oacc[i][cc][e] += pv[i] * vv[e];
            }
        }
    }

    __syncthreads();
    // Normalize and stage O into smem as Os[c][m] for coalesced output
#pragma unroll
    for (int i = 0; i < 4; i++) {
        float inv = 1.f / l[i];
#pragma unroll
        for (int cc = 0; cc < 4; cc++)
#pragma unroll
            for (int e = 0; e < 4; e++) {
                int c = cc * 64 + tx * 4 + e;
                Os[c * 68 + ty * 4 + i] = oacc[i][cc][e] * inv;
            }
    }
    __syncthreads();

    const float gm = gamma[0];
    const float* xb = x + b * CN;
    float* ob = out + b * CN;
    for (int idx = tid; idx < 16384; idx += 256) {
        int c = idx >> 6, m = idx & 63;
        int g = c * N_ + m0 + m;
        ob[g] = gm * Os[c * 68 + m] + xb[g];
    }
}

extern "C" void kernel_launch(void* const* d_in, const int* in_sizes, int n_in,
                              void* d_out, int out_size)
{
    const float* x     = (const float*)d_in[0];
    const float* Wq    = (const float*)d_in[1];
    const float* bq    = (const float*)d_in[2];
    const float* Wk    = (const float*)d_in[3];
    const float* bk    = (const float*)d_in[4];
    const float* Wv    = (const float*)d_in[5];
    const float* bv    = (const float*)d_in[6];
    const float* rh    = (const float*)d_in[7];
    const float* rw    = (const float*)d_in[8];
    const float* gamma = (const float*)d_in[9];
    float* out = (float*)d_out;

    dim3 gp(N_ / 64, C_ / 64, B_ * 3);
    proj_kernel<<<gp, 256>>>(x, Wq, bq, Wk, bk, Wv, bv, rh, rw);

    const int smem_bytes = 53760 * (int)sizeof(float);  // 215040 B
    cudaFuncSetAttribute(attn_kernel, cudaFuncAttributeMaxDynamicSharedMemorySize, smem_bytes);
    dim3 ga(N_ / 64, B_);
    attn_kernel<<<ga, 256, smem_bytes>>>(x, gamma, out);
}

// round 12
// speedup vs baseline: 1.7999x; 1.7977x over previous
#include <cuda_runtime.h>
#include <cuda_bf16.h>
#include <math_constants.h>
#include <cstdint>

#define B_ 4
#define C_ 256
#define N_ 4096
#define CN (C_*N_)

// bf16 hi/lo operands, all in [b][n][c] row-major (c contiguous)
static __device__ __align__(16) __nv_bfloat16 g_qh[B_*CN], g_ql[B_*CN];
static __device__ __align__(16) __nv_bfloat16 g_kh[B_*CN], g_kl[B_*CN];
static __device__ __align__(16) __nv_bfloat16 g_vh[B_*CN], g_vl[B_*CN];

// ---------------------------------------------------------------------------
// helpers (sm_80-level PTX only: cp.async, ldmatrix, mma.sync bf16)
// ---------------------------------------------------------------------------
__device__ __forceinline__ uint32_t smem_u32(const void* p){
    uint32_t a;
    asm("{ .reg .u64 t; cvta.to.shared.u64 t, %1; cvt.u32.u64 %0, t; }" : "=r"(a) : "l"(p));
    return a;
}
__device__ __forceinline__ void cpa16(uint32_t dst, const void* src){
    asm volatile("cp.async.cg.shared.global [%0], [%1], 16;" :: "r"(dst), "l"(src));
}
#define CP_COMMIT() asm volatile("cp.async.commit_group;" ::: "memory")
#define CP_WAIT0()  asm volatile("cp.async.wait_group 0;" ::: "memory")

__device__ __forceinline__ void ldsm4(uint32_t* r, uint32_t a){
    asm volatile("ldmatrix.sync.aligned.m8n8.x4.shared.b16 {%0,%1,%2,%3}, [%4];"
        : "=r"(r[0]),"=r"(r[1]),"=r"(r[2]),"=r"(r[3]) : "r"(a));
}
__device__ __forceinline__ void ldsm4t(uint32_t* r, uint32_t a){
    asm volatile("ldmatrix.sync.aligned.m8n8.x4.trans.shared.b16 {%0,%1,%2,%3}, [%4];"
        : "=r"(r[0]),"=r"(r[1]),"=r"(r[2]),"=r"(r[3]) : "r"(a));
}
__device__ __forceinline__ void mma16816(float* d, const uint32_t* a, const uint32_t* b){
    asm volatile("mma.sync.aligned.m16n8k16.row.col.f32.bf16.bf16.f32 "
        "{%0,%1,%2,%3}, {%4,%5,%6,%7}, {%8,%9}, {%0,%1,%2,%3};"
        : "+f"(d[0]),"+f"(d[1]),"+f"(d[2]),"+f"(d[3])
        : "r"(a[0]),"r"(a[1]),"r"(a[2]),"r"(a[3]),"r"(b[0]),"r"(b[1]));
}
__device__ __forceinline__ uint32_t pack2(__nv_bfloat16 a, __nv_bfloat16 b){
    uint32_t lo = *reinterpret_cast<uint16_t*>(&a);
    uint32_t hi = *reinterpret_cast<uint16_t*>(&b);
    return lo | (hi << 16);
}
// XOR swizzle: rows of 512B (32 x 16B chunks); conflict-free ldmatrix
__device__ __forceinline__ uint32_t swz(uint32_t base, int row, int chunk){
    return base + row * 512 + (((chunk ^ row) & 7) << 4) + ((chunk & 24) << 4);
}

// ---------------------------------------------------------------------------
// Projection kernel (FFMA GEMM) -> bf16 hi/lo splits, all [b][n][c]
// ---------------------------------------------------------------------------
__global__ __launch_bounds__(256, 1)
void proj_kernel(const float* __restrict__ x,
                 const float* __restrict__ Wq, const float* __restrict__ bq,
                 const float* __restrict__ Wk, const float* __restrict__ bk,
                 const float* __restrict__ Wv, const float* __restrict__ bv,
                 const float* __restrict__ rh, const float* __restrict__ rw)
{
    __shared__ float Ws[64][65];
    __shared__ float Xs[64][64];

    const int tid = threadIdx.x;
    const int tx = tid & 15, ty = tid >> 4;
    const int n0 = blockIdx.x * 64;
    const int o0 = blockIdx.y * 64;
    const int b  = blockIdx.z / 3;
    const int p  = blockIdx.z % 3;

    const float* W    = (p == 0) ? Wq : ((p == 1) ? Wk : Wv);
    const float* bias = (p == 0) ? bq : ((p == 1) ? bk : bv);
    const float* xb = x + (size_t)b * CN;

    float acc[4][4];
#pragma unroll
    for (int i = 0; i < 4; i++)
#pragma unroll
        for (int j = 0; j < 4; j++) acc[i][j] = 0.f;

    for (int c0 = 0; c0 < C_; c0 += 64) {
        for (int idx = tid; idx < 4096; idx += 256) {
            int r = idx >> 6, cc = idx & 63;
            Ws[r][cc] = W[(o0 + r) * C_ + c0 + cc];
            Xs[r][cc] = xb[(size_t)(c0 + r) * N_ + n0 + cc];
        }
        __syncthreads();
#pragma unroll 4
        for (int kc = 0; kc < 64; kc++) {
            float4 xv = *(const float4*)&Xs[kc][tx * 4];
            float w0 = Ws[ty*4+0][kc], w1 = Ws[ty*4+1][kc], w2 = Ws[ty*4+2][kc], w3 = Ws[ty*4+3][kc];
            acc[0][0]+=w0*xv.x; acc[0][1]+=w0*xv.y; acc[0][2]+=w0*xv.z; acc[0][3]+=w0*xv.w;
            acc[1][0]+=w1*xv.x; acc[1][1]+=w1*xv.y; acc[1][2]+=w1*xv.z; acc[1][3]+=w1*xv.w;
            acc[2][0]+=w2*xv.x; acc[2][1]+=w2*xv.y; acc[2][2]+=w2*xv.z; acc[2][3]+=w2*xv.w;
            acc[3][0]+=w3*xv.x; acc[3][1]+=w3*xv.y; acc[3][2]+=w3*xv.z; acc[3][3]+=w3*xv.w;
        }
        __syncthreads();
    }

    // stage transposed [n_local][o_local] hi+lo in smem, then coalesced [n][c] write
    __nv_bfloat16* stage = (__nv_bfloat16*)Ws;  // 16640B >= 2*4096*2B
#pragma unroll
    for (int i = 0; i < 4; i++) {
        int c = o0 + ty * 4 + i;
        float bv_ = bias[c];
#pragma unroll
        for (int j = 0; j < 4; j++) {
            float t = acc[i][j] + bv_;
            if (p == 1) t += rh[c * 64 + (n0 >> 6)] + rw[c * 64 + tx * 4 + j];
            int nl = tx * 4 + j, ol = ty * 4 + i;
            __nv_bfloat16 h = __float2bfloat16(t);
            stage[nl * 64 + ol]        = h;
            stage[4096 + nl * 64 + ol] = __float2bfloat16(t - __bfloat162float(h));
        }
    }
    __syncthreads();
    __nv_bfloat16* oh = ((p == 0) ? g_qh : ((p == 1) ? g_kh : g_vh)) + (size_t)b * CN;
    __nv_bfloat16* ol = ((p == 0) ? g_ql : ((p == 1) ? g_kl : g_vl)) + (size_t)b * CN;
    const uint32_t* st = (const uint32_t*)stage;
    for (int idx = tid; idx < 2048; idx += 256) {
        int n = idx >> 5, w2 = idx & 31;
        ((uint32_t*)(oh + (size_t)(n0 + n) * C_ + o0))[w2] = st[idx];
        ((uint32_t*)(ol + (size_t)(n0 + n) * C_ + o0))[w2] = st[2048 + idx];
    }
}

// ---------------------------------------------------------------------------
// mma.sync flash-attention. grid (32, 4), 256 threads (8 warps x 16 query rows).
// SMEM: Qh 0..64K, Ql 64..128K, Kh 128..144K, Kl 144..160K, Vh 160..176K,
//       Vl 176..192K.  All tiles: rows of 512B (256ch x bf16), XOR-swizzled.
// Epilogue reuses smem as Os[256][132] floats (135KB).
// ---------------------------------------------------------------------------
#define S_QH 0
#define S_QL 65536
#define S_KH 131072
#define S_KL 147456
#define S_VH 163840
#define S_VL 180224
#define SMEM_SZ 196608

__global__ __launch_bounds__(256, 1)
void attn_kernel(const float* __restrict__ x,
                 const float* __restrict__ gamma,
                 float* __restrict__ out)
{
    extern __shared__ __align__(1024) char sm[];
    const uint32_t sb = smem_u32(sm);
    const int tid = threadIdx.x;
    const int wid = tid >> 5, L = tid & 31;
    const int b = blockIdx.y, m0 = blockIdx.x * 128;
    const int qb = wid * 16;

    // ---- load Q hi/lo (128 rows x 512B each) via cp.async ----
    {
        const __nv_bfloat16* qh = g_qh + (size_t)b * CN + (size_t)m0 * C_;
        const __nv_bfloat16* ql = g_ql + (size_t)b * CN + (size_t)m0 * C_;
#pragma unroll
        for (int it = 0; it < 16; it++) {
            int idx = tid + it * 256;
            int row = idx >> 5, ch = idx & 31;
            cpa16(swz(sb + S_QH, row, ch), qh + idx * 8);
            cpa16(swz(sb + S_QL, row, ch), ql + idx * 8);
        }
        CP_COMMIT(); CP_WAIT0();
        __syncthreads();
    }

    float O_[128];
#pragma unroll
    for (int i = 0; i < 128; i++) O_[i] = 0.f;
    float mA = -CUDART_INF_F, mB = -CUDART_INF_F, lA = 0.f, lB = 0.f;

    // ldmatrix lane address components
    const int rowQ  = qb + (L & 15);            // A-frag rows
    const int hiA   = L >> 4;                   // chunk +0/+1 selector
    const int rowK0 = (L & 7) + ((L >> 1) & 8); // B-frag keys 0-15 group
    const int rowK1 = 16 + rowK0;
    const int chKs  = (L >> 3) & 1;
    const int rowV  = (L & 15);

    const __nv_bfloat16* khb = g_kh + (size_t)b * CN;
    const __nv_bfloat16* klb = g_kl + (size_t)b * CN;
    const __nv_bfloat16* vhb = g_vh + (size_t)b * CN;
    const __nv_bfloat16* vlb = g_vl + (size_t)b * CN;

    for (int kt = 0; kt < 128; kt++) {
        const int k0 = kt * 32;
        __syncthreads();   // everyone done with previous K/V tile
        // ---- load K/V hi/lo tile (32 keys x 512B each array) ----
        {
            const __nv_bfloat16* kh = khb + (size_t)k0 * C_;
            const __nv_bfloat16* kl = klb + (size_t)k0 * C_;
            const __nv_bfloat16* vh = vhb + (size_t)k0 * C_;
            const __nv_bfloat16* vl = vlb + (size_t)k0 * C_;
#pragma unroll
            for (int it = 0; it < 4; it++) {
                int idx = tid + it * 256;
                int row = idx >> 5, ch = idx & 31;
                cpa16(swz(sb + S_KH, row, ch), kh + idx * 8);
                cpa16(swz(sb + S_KL, row, ch), kl + idx * 8);
                cpa16(swz(sb + S_VH, row, ch), vh + idx * 8);
                cpa16(swz(sb + S_VL, row, ch), vl + idx * 8);
            }
            CP_COMMIT(); CP_WAIT0();
            __syncthreads();
        }

        // ---- S = Qh*Kh + Qh*Kl + Ql*Kh  over 256 channels, 32 keys ----
        float sacc[4][4];
#pragma unroll
        for (int t = 0; t < 4; t++)
#pragma unroll
            for (int e = 0; e < 4; e++) sacc[t][e] = 0.f;

#pragma unroll 4
        for (int kc = 0; kc < 16; kc++) {
            uint32_t ah[4], al[4], b0h[4], b1h[4], b0l[4], b1l[4];
            int chA = 2 * kc + hiA;
            int chB = 2 * kc + chKs;
            ldsm4(ah,  swz(sb + S_QH, rowQ,  chA));
            ldsm4(al,  swz(sb + S_QL, rowQ,  chA));
            ldsm4(b0h, swz(sb + S_KH, rowK0, chB));
            ldsm4(b1h, swz(sb + S_KH, rowK1, chB));
            ldsm4(b0l, swz(sb + S_KL, rowK0, chB));
            ldsm4(b1l, swz(sb + S_KL, rowK1, chB));
            mma16816(sacc[0], ah, b0h);     mma16816(sacc[1], ah, b0h + 2);
            mma16816(sacc[2], ah, b1h);     mma16816(sacc[3], ah, b1h + 2);
            mma16816(sacc[0], ah, b0l);     mma16816(sacc[1], ah, b0l + 2);
            mma16816(sacc[2], ah, b1l);     mma16816(sacc[3], ah, b1l + 2);
            mma16816(sacc[0], al, b0h);     mma16816(sacc[1], al, b0h + 2);
            mma16816(sacc[2], al, b1h);     mma16816(sacc[3], al, b1h + 2);
        }

        // ---- online softmax (warp-local; rows rA=L/4, rB=rA+8) ----
        float tmA = -CUDART_INF_F, tmB = -CUDART_INF_F;
#pragma unroll
        for (int t = 0; t < 4; t++) {
            tmA = fmaxf(tmA, fmaxf(sacc[t][0], sacc[t][1]));
            tmB = fmaxf(tmB, fmaxf(sacc[t][2], sacc[t][3]));
        }
        tmA = fmaxf(tmA, __shfl_xor_sync(0xffffffffu, tmA, 1));
        tmA = fmaxf(tmA, __shfl_xor_sync(0xffffffffu, tmA, 2));
        tmB = fmaxf(tmB, __shfl_xor_sync(0xffffffffu, tmB, 1));
        tmB = fmaxf(tmB, __shfl_xor_sync(0xffffffffu, tmB, 2));
        float nmA = fmaxf(mA, tmA), nmB = fmaxf(mB, tmB);
        float facA = __expf(mA - nmA), facB = __expf(mB - nmB);
        mA = nmA; mB = nmB;

        uint32_t ph[2][4], pl[2][4];
        float sumA = 0.f, sumB = 0.f;
#pragma unroll
        for (int t = 0; t < 4; t++) {
            float p0 = __expf(sacc[t][0] - nmA), p1 = __expf(sacc[t][1] - nmA);
            float p2 = __expf(sacc[t][2] - nmB), p3 = __expf(sacc[t][3] - nmB);
            sumA += p0 + p1; sumB += p2 + p3;
            __nv_bfloat16 h0 = __float2bfloat16(p0), h1 = __float2bfloat16(p1);
            __nv_bfloat16 h2 = __float2bfloat16(p2), h3 = __float2bfloat16(p3);
            int j = t >> 1, s = t & 1;
            ph[j][2*s]   = pack2(h0, h1);
            ph[j][2*s+1] = pack2(h2, h3);
            pl[j][2*s]   = pack2(__float2bfloat16(p0 - __bfloat162float(h0)),
                                 __float2bfloat16(p1 - __bfloat162float(h1)));
            pl[j][2*s+1] = pack2(__float2bfloat16(p2 - __bfloat162float(h2)),
                                 __float2bfloat16(p3 - __bfloat162float(h3)));
        }
        sumA += __shfl_xor_sync(0xffffffffu, sumA, 1);
        sumA += __shfl_xor_sync(0xffffffffu, sumA, 2);
        sumB += __shfl_xor_sync(0xffffffffu, sumB, 1);
        sumB += __shfl_xor_sync(0xffffffffu, sumB, 2);
        lA = lA * facA + sumA;
        lB = lB * facB + sumB;

        // rescale O
#pragma unroll
        for (int t = 0; t < 32; t++) {
            O_[4*t+0] *= facA; O_[4*t+1] *= facA;
            O_[4*t+2] *= facB; O_[4*t+3] *= facB;
        }

        // ---- O += Ph*Vh + Ph*Vl + Pl*Vh  (k = 32 keys, n = 256 channels) ----
#pragma unroll
        for (int j = 0; j < 2; j++) {
#pragma unroll 4
            for (int ng = 0; ng < 16; ng++) {
                uint32_t bh[4], bl[4];
                int rV = j * 16 + rowV;
                int cV = 2 * ng + hiA;
                ldsm4t(bh, swz(sb + S_VH, rV, cV));
                ldsm4t(bl, swz(sb + S_VL, rV, cV));
                float* o0 = O_ + (2 * ng) * 4;
                float* o1 = O_ + (2 * ng + 1) * 4;
                mma16816(o0, ph[j], bh);     mma16816(o1, ph[j], bh + 2);
                mma16816(o0, ph[j], bl);     mma16816(o1, ph[j], bl + 2);
                mma16816(o0, pl[j], bh);     mma16816(o1, pl[j], bh + 2);
            }
        }
    }

    // ---- epilogue: normalize, stage Os[c][m] (stride 132), fused residual ----
    __syncthreads();
    {
        float* Os = (float*)sm;
        float invA = 1.f / lA, invB = 1.f / lB;
        int mAi = qb + (L >> 2), mBi = mAi + 8;
        int cb = (L & 3) * 2;
#pragma unroll
        for (int t = 0; t < 32; t++) {
            int c = t * 8 + cb;
            Os[c * 132 + mAi]       = O_[4*t+0] * invA;
            Os[(c + 1) * 132 + mAi] = O_[4*t+1] * invA;
            Os[c * 132 + mBi]       = O_[4*t+2] * invB;
            Os[(c + 1) * 132 + mBi] = O_[4*t+3] * invB;
        }
    }
    __syncthreads();
    {
        const float gm = gamma[0];
        const float* Os = (const float*)sm;
        const float* xb = x + (size_t)b * CN;
        float* ob = out + (size_t)b * CN;
        for (int idx = tid; idx < 32768; idx += 256) {
            int c = idx >> 7, m = idx & 127;
            size_t g = (size_t)c * N_ + m0 + m;
            ob[g] = gm * Os[c * 132 + m] + xb[g];
        }
    }
}

extern "C" void kernel_launch(void* const* d_in, const int* in_sizes, int n_in,
                              void* d_out, int out_size)
{
    const float* x     = (const float*)d_in[0];
    const float* Wq    = (const float*)d_in[1];
    const float* bq    = (const float*)d_in[2];
    const float* Wk    = (const float*)d_in[3];
    const float* bk    = (const float*)d_in[4];
    const float* Wv    = (const float*)d_in[5];
    const float* bv    = (const float*)d_in[6];
    const float* rh    = (const float*)d_in[7];
    const float* rw    = (const float*)d_in[8];
    const float* gamma = (const float*)d_in[9];
    float* out = (float*)d_out;

    dim3 gp(N_ / 64, C_ / 64, B_ * 3);
    proj_kernel<<<gp, 256>>>(x, Wq, bq, Wk, bk, Wv, bv, rh, rw);

    cudaFuncSetAttribute(attn_kernel, cudaFuncAttributeMaxDynamicSharedMemorySize, SMEM_SZ);
    dim3 ga(N_ / 128, B_);
    attn_kernel<<<ga, 256, SMEM_SZ>>>(x, gamma, out);
}

// round 13
// speedup vs baseline: 1.8394x; 1.0220x over previous
#include <cuda_runtime.h>
#include <cuda_bf16.h>
#include <math_constants.h>
#include <cstdint>

#define B_ 4
#define C_ 256
#define N_ 4096
#define CN (C_*N_)

// bf16 hi/lo operands, all in [b][n][c] row-major (c contiguous)
static __device__ __align__(16) __nv_bfloat16 g_qh[B_*CN], g_ql[B_*CN];
static __device__ __align__(16) __nv_bfloat16 g_kh[B_*CN], g_kl[B_*CN];
static __device__ __align__(16) __nv_bfloat16 g_vh[B_*CN], g_vl[B_*CN];

// ---------------------------------------------------------------------------
// helpers (sm_80-level PTX only: cp.async, ldmatrix, mma.sync bf16)
// ---------------------------------------------------------------------------
__device__ __forceinline__ uint32_t smem_u32(const void* p){
    uint32_t a;
    asm("{ .reg .u64 t; cvta.to.shared.u64 t, %1; cvt.u32.u64 %0, t; }" : "=r"(a) : "l"(p));
    return a;
}
__device__ __forceinline__ void cpa16(uint32_t dst, const void* src){
    asm volatile("cp.async.cg.shared.global [%0], [%1], 16;" :: "r"(dst), "l"(src));
}
#define CP_COMMIT() asm volatile("cp.async.commit_group;" ::: "memory")
#define CP_WAIT1()  asm volatile("cp.async.wait_group 1;" ::: "memory")

__device__ __forceinline__ void ldsm4(uint32_t* r, uint32_t a){
    asm volatile("ldmatrix.sync.aligned.m8n8.x4.shared.b16 {%0,%1,%2,%3}, [%4];"
        : "=r"(r[0]),"=r"(r[1]),"=r"(r[2]),"=r"(r[3]) : "r"(a));
}
__device__ __forceinline__ void ldsm4t(uint32_t* r, uint32_t a){
    asm volatile("ldmatrix.sync.aligned.m8n8.x4.trans.shared.b16 {%0,%1,%2,%3}, [%4];"
        : "=r"(r[0]),"=r"(r[1]),"=r"(r[2]),"=r"(r[3]) : "r"(a));
}
__device__ __forceinline__ void mma16816(float* d, const uint32_t* a, const uint32_t* b){
    asm volatile("mma.sync.aligned.m16n8k16.row.col.f32.bf16.bf16.f32 "
        "{%0,%1,%2,%3}, {%4,%5,%6,%7}, {%8,%9}, {%0,%1,%2,%3};"
        : "+f"(d[0]),"+f"(d[1]),"+f"(d[2]),"+f"(d[3])
        : "r"(a[0]),"r"(a[1]),"r"(a[2]),"r"(a[3]),"r"(b[0]),"r"(b[1]));
}
__device__ __forceinline__ uint32_t pack2(__nv_bfloat16 a, __nv_bfloat16 b){
    uint32_t lo = *reinterpret_cast<uint16_t*>(&a);
    uint32_t hi = *reinterpret_cast<uint16_t*>(&b);
    return lo | (hi << 16);
}
// XOR swizzle: rows of 512B (32 x 16B chunks); conflict-free ldmatrix
__device__ __forceinline__ uint32_t swz(uint32_t base, int row, int chunk){
    return base + row * 512 + (((chunk ^ row) & 7) << 4) + ((chunk & 24) << 4);
}

// ---------------------------------------------------------------------------
// Projection kernel (FFMA GEMM) -> bf16 hi/lo splits, all [b][n][c]
// ---------------------------------------------------------------------------
__global__ __launch_bounds__(256, 1)
void proj_kernel(const float* __restrict__ x,
                 const float* __restrict__ Wq, const float* __restrict__ bq,
                 const float* __restrict__ Wk, const float* __restrict__ bk,
                 const float* __restrict__ Wv, const float* __restrict__ bv,
                 const float* __restrict__ rh, const float* __restrict__ rw)
{
    __shared__ float Ws[64][65];
    __shared__ float Xs[64][64];

    const int tid = threadIdx.x;
    const int tx = tid & 15, ty = tid >> 4;
    const int n0 = blockIdx.x * 64;
    const int o0 = blockIdx.y * 64;
    const int b  = blockIdx.z / 3;
    const int p  = blockIdx.z % 3;

    const float* W    = (p == 0) ? Wq : ((p == 1) ? Wk : Wv);
    const float* bias = (p == 0) ? bq : ((p == 1) ? bk : bv);
    const float* xb = x + (size_t)b * CN;

    float acc[4][4];
#pragma unroll
    for (int i = 0; i < 4; i++)
#pragma unroll
        for (int j = 0; j < 4; j++) acc[i][j] = 0.f;

    for (int c0 = 0; c0 < C_; c0 += 64) {
        for (int idx = tid; idx < 4096; idx += 256) {
            int r = idx >> 6, cc = idx & 63;
            Ws[r][cc] = W[(o0 + r) * C_ + c0 + cc];
            Xs[r][cc] = xb[(size_t)(c0 + r) * N_ + n0 + cc];
        }
        __syncthreads();
#pragma unroll 4
        for (int kc = 0; kc < 64; kc++) {
            float4 xv = *(const float4*)&Xs[kc][tx * 4];
            float w0 = Ws[ty*4+0][kc], w1 = Ws[ty*4+1][kc], w2 = Ws[ty*4+2][kc], w3 = Ws[ty*4+3][kc];
            acc[0][0]+=w0*xv.x; acc[0][1]+=w0*xv.y; acc[0][2]+=w0*xv.z; acc[0][3]+=w0*xv.w;
            acc[1][0]+=w1*xv.x; acc[1][1]+=w1*xv.y; acc[1][2]+=w1*xv.z; acc[1][3]+=w1*xv.w;
            acc[2][0]+=w2*xv.x; acc[2][1]+=w2*xv.y; acc[2][2]+=w2*xv.z; acc[2][3]+=w2*xv.w;
            acc[3][0]+=w3*xv.x; acc[3][1]+=w3*xv.y; acc[3][2]+=w3*xv.z; acc[3][3]+=w3*xv.w;
        }
        __syncthreads();
    }

    // stage transposed [n_local][o_local] hi+lo in smem, then coalesced [n][c] write
    __nv_bfloat16* stage = (__nv_bfloat16*)Ws;  // 16640B >= 2*4096*2B
#pragma unroll
    for (int i = 0; i < 4; i++) {
        int c = o0 + ty * 4 + i;
        float bv_ = bias[c];
#pragma unroll
        for (int j = 0; j < 4; j++) {
            float t = acc[i][j] + bv_;
            if (p == 1) t += rh[c * 64 + (n0 >> 6)] + rw[c * 64 + tx * 4 + j];
            int nl = tx * 4 + j, ol = ty * 4 + i;
            __nv_bfloat16 h = __float2bfloat16(t);
            stage[nl * 64 + ol]        = h;
            stage[4096 + nl * 64 + ol] = __float2bfloat16(t - __bfloat162float(h));
        }
    }
    __syncthreads();
    __nv_bfloat16* oh = ((p == 0) ? g_qh : ((p == 1) ? g_kh : g_vh)) + (size_t)b * CN;
    __nv_bfloat16* ol = ((p == 0) ? g_ql : ((p == 1) ? g_kl : g_vl)) + (size_t)b * CN;
    const uint32_t* st = (const uint32_t*)stage;
    for (int idx = tid; idx < 2048; idx += 256) {
        int n = idx >> 5, w2 = idx & 31;
        ((uint32_t*)(oh + (size_t)(n0 + n) * C_ + o0))[w2] = st[idx];
        ((uint32_t*)(ol + (size_t)(n0 + n) * C_ + o0))[w2] = st[2048 + idx];
    }
}

// ---------------------------------------------------------------------------
// mma.sync flash-attention, 2-stage pipelined 16-key tiles.
// grid (32, 4), 256 threads (8 warps x 16 query rows).
// SMEM: Qh 0..64K, Ql 64..128K, KV stages @128K: 2 x 32K
//   each stage: Kh +0, Kl +8K, Vh +16K, Vl +24K  (16 rows x 512B, swizzled)
// Epilogue reuses smem as Os[256][132] floats (135KB).
// ---------------------------------------------------------------------------
#define S_QH 0
#define S_QL 65536
#define S_KV 131072
#define KV_STRIDE 32768
#define KV_KH 0
#define KV_KL 8192
#define KV_VH 16384
#define KV_VL 24576
#define SMEM_SZ 196608
#define NT 256           /* 4096 keys / 16 */

__global__ __launch_bounds__(256, 1)
void attn_kernel(const float* __restrict__ x,
                 const float* __restrict__ gamma,
                 float* __restrict__ out)
{
    extern __shared__ __align__(1024) char sm[];
    const uint32_t sb = smem_u32(sm);
    const int tid = threadIdx.x;
    const int wid = tid >> 5, L = tid & 31;
    const int b = blockIdx.y, m0 = blockIdx.x * 128;
    const int qb = wid * 16;

    const __nv_bfloat16* khb = g_kh + (size_t)b * CN;
    const __nv_bfloat16* klb = g_kl + (size_t)b * CN;
    const __nv_bfloat16* vhb = g_vh + (size_t)b * CN;
    const __nv_bfloat16* vlb = g_vl + (size_t)b * CN;

    // per-thread KV load slots: 2 chunks per array (16 rows x 32 chunks = 512)
    const int i0 = tid, i1 = tid + 256;
    const int r0 = i0 >> 5, c0_ = i0 & 31, r1 = i1 >> 5, c1_ = i1 & 31;

    // ---- prologue: Q hi/lo (group 0), KV tile 0 (group 1) ----
    {
        const __nv_bfloat16* qh = g_qh + (size_t)b * CN + (size_t)m0 * C_;
        const __nv_bfloat16* ql = g_ql + (size_t)b * CN + (size_t)m0 * C_;
#pragma unroll
        for (int it = 0; it < 16; it++) {
            int idx = tid + it * 256;
            int row = idx >> 5, ch = idx & 31;
            cpa16(swz(sb + S_QH, row, ch), qh + idx * 8);
            cpa16(swz(sb + S_QL, row, ch), ql + idx * 8);
        }
        CP_COMMIT();
    }
    {
        uint32_t st = sb + S_KV;
        cpa16(swz(st + KV_KH, r0, c0_), khb + i0 * 8);
        cpa16(swz(st + KV_KH, r1, c1_), khb + i1 * 8);
        cpa16(swz(st + KV_KL, r0, c0_), klb + i0 * 8);
        cpa16(swz(st + KV_KL, r1, c1_), klb + i1 * 8);
        cpa16(swz(st + KV_VH, r0, c0_), vhb + i0 * 8);
        cpa16(swz(st + KV_VH, r1, c1_), vhb + i1 * 8);
        cpa16(swz(st + KV_VL, r0, c0_), vlb + i0 * 8);
        cpa16(swz(st + KV_VL, r1, c1_), vlb + i1 * 8);
        CP_COMMIT();
    }

    float O_[128];
#pragma unroll
    for (int i = 0; i < 128; i++) O_[i] = 0.f;
    float mA = -CUDART_INF_F, mB = -CUDART_INF_F, lA = 0.f, lB = 0.f;

    // ldmatrix lane address components
    const int rowQ  = qb + (L & 15);
    const int hiA   = L >> 4;
    const int rowK0 = (L & 7) + ((L >> 1) & 8);  // keys 0-15 group
    const int chKs  = (L >> 3) & 1;
    const int rowV  = (L & 15);

    for (int kt = 0; kt < NT; kt++) {
        const uint32_t st = sb + S_KV + (kt & 1) * KV_STRIDE;
        // ---- prefetch tile kt+1 into the other stage ----
        if (kt + 1 < NT) {
            const uint32_t sn = sb + S_KV + ((kt + 1) & 1) * KV_STRIDE;
            const size_t off = (size_t)(kt + 1) * 16 * C_;
            cpa16(swz(sn + KV_KH, r0, c0_), khb + off + i0 * 8);
            cpa16(swz(sn + KV_KH, r1, c1_), khb + off + i1 * 8);
            cpa16(swz(sn + KV_KL, r0, c0_), klb + off + i0 * 8);
            cpa16(swz(sn + KV_KL, r1, c1_), klb + off + i1 * 8);
            cpa16(swz(sn + KV_VH, r0, c0_), vhb + off + i0 * 8);
            cpa16(swz(sn + KV_VH, r1, c1_), vhb + off + i1 * 8);
            cpa16(swz(sn + KV_VL, r0, c0_), vlb + off + i0 * 8);
            cpa16(swz(sn + KV_VL, r1, c1_), vlb + off + i1 * 8);
        }
        CP_COMMIT();
        CP_WAIT1();          // current tile (and Q on kt=0) arrived; newest stays in flight
        __syncthreads();

        // ---- S = Qh*Kh + Qh*Kl + Ql*Kh  over 256 channels, 16 keys ----
        float sacc[2][4];
#pragma unroll
        for (int t = 0; t < 2; t++)
#pragma unroll
            for (int e = 0; e < 4; e++) sacc[t][e] = 0.f;

#pragma unroll 4
        for (int kc = 0; kc < 16; kc++) {
            uint32_t ah[4], al[4], bh[4], bl[4];
            int chA = 2 * kc + hiA;
            int chB = 2 * kc + chKs;
            ldsm4(ah, swz(sb + S_QH, rowQ, chA));
            ldsm4(al, swz(sb + S_QL, rowQ, chA));
            ldsm4(bh, swz(st + KV_KH, rowK0, chB));
            ldsm4(bl, swz(st + KV_KL, rowK0, chB));
            mma16816(sacc[0], ah, bh);   mma16816(sacc[1], ah, bh + 2);
            mma16816(sacc[0], ah, bl);   mma16816(sacc[1], ah, bl + 2);
            mma16816(sacc[0], al, bh);   mma16816(sacc[1], al, bh + 2);
        }

        // ---- online softmax (warp-local; rows rA=L>>2, rB=rA+8) ----
        float tmA = fmaxf(fmaxf(sacc[0][0], sacc[0][1]), fmaxf(sacc[1][0], sacc[1][1]));
        float tmB = fmaxf(fmaxf(sacc[0][2], sacc[0][3]), fmaxf(sacc[1][2], sacc[1][3]));
        tmA = fmaxf(tmA, __shfl_xor_sync(0xffffffffu, tmA, 1));
        tmA = fmaxf(tmA, __shfl_xor_sync(0xffffffffu, tmA, 2));
        tmB = fmaxf(tmB, __shfl_xor_sync(0xffffffffu, tmB, 1));
        tmB = fmaxf(tmB, __shfl_xor_sync(0xffffffffu, tmB, 2));
        float nmA = fmaxf(mA, tmA), nmB = fmaxf(mB, tmB);
        float facA = __expf(mA - nmA), facB = __expf(mB - nmB);
        mA = nmA; mB = nmB;

        uint32_t ph[4], pl[4];
        float sumA = 0.f, sumB = 0.f;
#pragma unroll
        for (int t = 0; t < 2; t++) {
            float p0 = __expf(sacc[t][0] - nmA), p1 = __expf(sacc[t][1] - nmA);
            float p2 = __expf(sacc[t][2] - nmB), p3 = __expf(sacc[t][3] - nmB);
            sumA += p0 + p1; sumB += p2 + p3;
            __nv_bfloat16 h0 = __float2bfloat16(p0), h1 = __float2bfloat16(p1);
            __nv_bfloat16 h2 = __float2bfloat16(p2), h3 = __float2bfloat16(p3);
            ph[2*t]   = pack2(h0, h1);
            ph[2*t+1] = pack2(h2, h3);
            pl[2*t]   = pack2(__float2bfloat16(p0 - __bfloat162float(h0)),
                              __float2bfloat16(p1 - __bfloat162float(h1)));
            pl[2*t+1] = pack2(__float2bfloat16(p2 - __bfloat162float(h2)),
                              __float2bfloat16(p3 - __bfloat162float(h3)));
        }
        sumA += __shfl_xor_sync(0xffffffffu, sumA, 1);
        sumA += __shfl_xor_sync(0xffffffffu, sumA, 2);
        sumB += __shfl_xor_sync(0xffffffffu, sumB, 1);
        sumB += __shfl_xor_sync(0xffffffffu, sumB, 2);
        lA = lA * facA + sumA;
        lB = lB * facB + sumB;

        // rescale O only when a running max actually moved
        if (facA < 1.f || facB < 1.f) {
#pragma unroll
            for (int t = 0; t < 32; t++) {
                O_[4*t+0] *= facA; O_[4*t+1] *= facA;
                O_[4*t+2] *= facB; O_[4*t+3] *= facB;
            }
        }

        // ---- O += Ph*Vh + Ph*Vl + Pl*Vh  (k = 16 keys, n = 256 channels) ----
#pragma unroll 4
        for (int ng = 0; ng < 16; ng++) {
            uint32_t bh[4], bl[4];
            int cV = 2 * ng + hiA;
            ldsm4t(bh, swz(st + KV_VH, rowV, cV));
            ldsm4t(bl, swz(st + KV_VL, rowV, cV));
            float* o0 = O_ + (2 * ng) * 4;
            float* o1 = O_ + (2 * ng + 1) * 4;
            mma16816(o0, ph, bh);   mma16816(o1, ph, bh + 2);
            mma16816(o0, ph, bl);   mma16816(o1, ph, bl + 2);
            mma16816(o0, pl, bh);   mma16816(o1, pl, bh + 2);
        }
        __syncthreads();   // done reading stage before it is overwritten next+1 iter
    }

    // ---- epilogue: normalize, stage Os[c][m] (stride 132), fused residual ----
    __syncthreads();
    {
        float* Os = (float*)sm;
        float invA = 1.f / lA, invB = 1.f / lB;
        int mAi = qb + (L >> 2), mBi = mAi + 8;
        int cb = (L & 3) * 2;
#pragma unroll
        for (int t = 0; t < 32; t++) {
            int c = t * 8 + cb;
            Os[c * 132 + mAi]       = O_[4*t+0] * invA;
            Os[(c + 1) * 132 + mAi] = O_[4*t+1] * invA;
            Os[c * 132 + mBi]       = O_[4*t+2] * invB;
            Os[(c + 1) * 132 + mBi] = O_[4*t+3] * invB;
        }
    }
    __syncthreads();
    {
        const float gm = gamma[0];
        const float* Os = (const float*)sm;
        const float* xb = x + (size_t)b * CN;
        float* ob = out + (size_t)b * CN;
        for (int idx = tid; idx < 32768; idx += 256) {
            int c = idx >> 7, m = idx & 127;
            size_t g = (size_t)c * N_ + m0 + m;
            ob[g] = gm * Os[c * 132 + m] + xb[g];
        }
    }
}

extern "C" void kernel_launch(void* const* d_in, const int* in_sizes, int n_in,
                              void* d_out, int out_size)
{
    const float* x     = (const float*)d_in[0];
    const float* Wq    = (const float*)d_in[1];
    const float* bq    = (const float*)d_in[2];
    const float* Wk    = (const float*)d_in[3];
    const float* bk    = (const float*)d_in[4];
    const float* Wv    = (const float*)d_in[5];
    const float* bv    = (const float*)d_in[6];
    const float* rh    = (const float*)d_in[7];
    const float* rw    = (const float*)d_in[8];
    const float* gamma = (const float*)d_in[9];
    float* out = (float*)d_out;

    dim3 gp(N_ / 64, C_ / 64, B_ * 3);
    proj_kernel<<<gp, 256>>>(x, Wq, bq, Wk, bk, Wv, bv, rh, rw);

    cudaFuncSetAttribute(attn_kernel, cudaFuncAttributeMaxDynamicSharedMemorySize, SMEM_SZ);
    dim3 ga(N_ / 128, B_);
    attn_kernel<<<ga, 256, SMEM_SZ>>>(x, gamma, out);
}

// round 15
// speedup vs baseline: 3.2398x; 1.7613x over previous
#include <cuda_runtime.h>
#include <cuda_bf16.h>
#include <math_constants.h>
#include <cstdint>

#define B_ 4
#define C_ 256
#define N_ 4096
#define CN (C_*N_)

// bf16 hi/lo operands, all in [b][n][c] row-major (c contiguous)
static __device__ __align__(16) __nv_bfloat16 g_qh[B_*CN], g_ql[B_*CN];
static __device__ __align__(16) __nv_bfloat16 g_kh[B_*CN], g_kl[B_*CN];
static __device__ __align__(16) __nv_bfloat16 g_vh[B_*CN], g_vl[B_*CN];

// ---------------------------------------------------------------------------
// helpers (sm_80-level PTX only: cp.async, ldmatrix, mma.sync bf16)
// ---------------------------------------------------------------------------
__device__ __forceinline__ uint32_t smem_u32(const void* p){
    uint32_t a;
    asm("{ .reg .u64 t; cvta.to.shared.u64 t, %1; cvt.u32.u64 %0, t; }" : "=r"(a) : "l"(p));
    return a;
}
__device__ __forceinline__ void cpa16(uint32_t dst, const void* src){
    asm volatile("cp.async.cg.shared.global [%0], [%1], 16;" :: "r"(dst), "l"(src));
}
#define CP_COMMIT() asm volatile("cp.async.commit_group;" ::: "memory")
#define CP_WAIT0()  asm volatile("cp.async.wait_group 0;" ::: "memory")

__device__ __forceinline__ void ldsm4(uint32_t* r, uint32_t a){
    asm volatile("ldmatrix.sync.aligned.m8n8.x4.shared.b16 {%0,%1,%2,%3}, [%4];"
        : "=r"(r[0]),"=r"(r[1]),"=r"(r[2]),"=r"(r[3]) : "r"(a));
}
__device__ __forceinline__ void ldsm4t(uint32_t* r, uint32_t a){
    asm volatile("ldmatrix.sync.aligned.m8n8.x4.trans.shared.b16 {%0,%1,%2,%3}, [%4];"
        : "=r"(r[0]),"=r"(r[1]),"=r"(r[2]),"=r"(r[3]) : "r"(a));
}
__device__ __forceinline__ void mma16816(float* d, const uint32_t* a, const uint32_t* b){
    asm volatile("mma.sync.aligned.m16n8k16.row.col.f32.bf16.bf16.f32 "
        "{%0,%1,%2,%3}, {%4,%5,%6,%7}, {%8,%9}, {%0,%1,%2,%3};"
        : "+f"(d[0]),"+f"(d[1]),"+f"(d[2]),"+f"(d[3])
        : "r"(a[0]),"r"(a[1]),"r"(a[2]),"r"(a[3]),"r"(b[0]),"r"(b[1]));
}
__device__ __forceinline__ uint32_t pack2(__nv_bfloat16 a, __nv_bfloat16 b){
    uint32_t lo = *reinterpret_cast<uint16_t*>(&a);
    uint32_t hi = *reinterpret_cast<uint16_t*>(&b);
    return lo | (hi << 16);
}
// XOR swizzle: rows of 512B (32 x 16B chunks); conflict-free ldmatrix
__device__ __forceinline__ uint32_t swz(uint32_t base, int row, int chunk){
    return base + row * 512 + (((chunk ^ row) & 7) << 4) + ((chunk & 24) << 4);
}

// ---------------------------------------------------------------------------
// Projection kernel (FFMA GEMM) -> bf16 hi/lo splits, all [b][n][c]
// ---------------------------------------------------------------------------
__global__ __launch_bounds__(256, 1)
void proj_kernel(const float* __restrict__ x,
                 const float* __restrict__ Wq, const float* __restrict__ bq,
                 const float* __restrict__ Wk, const float* __restrict__ bk,
                 const float* __restrict__ Wv, const float* __restrict__ bv,
                 const float* __restrict__ rh, const float* __restrict__ rw)
{
    __shared__ float Ws[64][65];
    __shared__ float Xs[64][64];

    const int tid = threadIdx.x;
    const int tx = tid & 15, ty = tid >> 4;
    const int n0 = blockIdx.x * 64;
    const int o0 = blockIdx.y * 64;
    const int b  = blockIdx.z / 3;
    const int p  = blockIdx.z % 3;

    const float* W    = (p == 0) ? Wq : ((p == 1) ? Wk : Wv);
    const float* bias = (p == 0) ? bq : ((p == 1) ? bk : bv);
    const float* xb = x + (size_t)b * CN;

    float acc[4][4];
#pragma unroll
    for (int i = 0; i < 4; i++)
#pragma unroll
        for (int j = 0; j < 4; j++) acc[i][j] = 0.f;

    for (int c0 = 0; c0 < C_; c0 += 64) {
        for (int idx = tid; idx < 4096; idx += 256) {
            int r = idx >> 6, cc = idx & 63;
            Ws[r][cc] = W[(o0 + r) * C_ + c0 + cc];
            Xs[r][cc] = xb[(size_t)(c0 + r) * N_ + n0 + cc];
        }
        __syncthreads();
#pragma unroll 4
        for (int kc = 0; kc < 64; kc++) {
            float4 xv = *(const float4*)&Xs[kc][tx * 4];
            float w0 = Ws[ty*4+0][kc], w1 = Ws[ty*4+1][kc], w2 = Ws[ty*4+2][kc], w3 = Ws[ty*4+3][kc];
            acc[0][0]+=w0*xv.x; acc[0][1]+=w0*xv.y; acc[0][2]+=w0*xv.z; acc[0][3]+=w0*xv.w;
            acc[1][0]+=w1*xv.x; acc[1][1]+=w1*xv.y; acc[1][2]+=w1*xv.z; acc[1][3]+=w1*xv.w;
            acc[2][0]+=w2*xv.x; acc[2][1]+=w2*xv.y; acc[2][2]+=w2*xv.z; acc[2][3]+=w2*xv.w;
            acc[3][0]+=w3*xv.x; acc[3][1]+=w3*xv.y; acc[3][2]+=w3*xv.z; acc[3][3]+=w3*xv.w;
        }
        __syncthreads();
    }

    // stage transposed [n_local][o_local] hi+lo in smem, then coalesced [n][c] write
    __nv_bfloat16* stage = (__nv_bfloat16*)Ws;  // 16640B >= 2*4096*2B
#pragma unroll
    for (int i = 0; i < 4; i++) {
        int c = o0 + ty * 4 + i;
        float bv_ = bias[c];
#pragma unroll
        for (int j = 0; j < 4; j++) {
            float t = acc[i][j] + bv_;
            if (p == 1) t += rh[c * 64 + (n0 >> 6)] + rw[c * 64 + tx * 4 + j];
            int nl = tx * 4 + j, ol = ty * 4 + i;
            __nv_bfloat16 h = __float2bfloat16(t);
            stage[nl * 64 + ol]        = h;
            stage[4096 + nl * 64 + ol] = __float2bfloat16(t - __bfloat162float(h));
        }
    }
    __syncthreads();
    __nv_bfloat16* oh = ((p == 0) ? g_qh : ((p == 1) ? g_kh : g_vh)) + (size_t)b * CN;
    __nv_bfloat16* ol = ((p == 0) ? g_ql : ((p == 1) ? g_kl : g_vl)) + (size_t)b * CN;
    const uint32_t* st = (const uint32_t*)stage;
    for (int idx = tid; idx < 2048; idx += 256) {
        int n = idx >> 5, w2 = idx & 31;
        ((uint32_t*)(oh + (size_t)(n0 + n) * C_ + o0))[w2] = st[idx];
        ((uint32_t*)(ol + (size_t)(n0 + n) * C_ + o0))[w2] = st[2048 + idx];
    }
}

// ---------------------------------------------------------------------------
// mma.sync flash-attention, 2-stage pipelined 16-key tiles, ILP-optimized:
//  - 6 independent S accumulator chains (term x key-group)
//  - 2-deep ldmatrix software pipeline in S and PV loops
//  - single __syncthreads per tile
// grid (32, 4), 256 threads (8 warps x 16 query rows).
// SMEM: Qh 0..64K, Ql 64..128K, KV stages @128K: 2 x 32K
//   each stage: Kh +0, Kl +8K, Vh +16K, Vl +24K  (16 rows x 512B, swizzled)
// ---------------------------------------------------------------------------
#define S_QH 0
#define S_QL 65536
#define S_KV 131072
#define KV_STRIDE 32768
#define KV_KH 0
#define KV_KL 8192
#define KV_VH 16384
#define KV_VL 24576
#define SMEM_SZ 196608
#define NT 256           /* 4096 keys / 16 */

__global__ __launch_bounds__(256, 1)
void attn_kernel(const float* __restrict__ x,
                 const float* __restrict__ gamma,
                 float* __restrict__ out)
{
    extern __shared__ __align__(1024) char sm[];
    const uint32_t sb = smem_u32(sm);
    const int tid = threadIdx.x;
    const int wid = tid >> 5, L = tid & 31;
    const int b = blockIdx.y, m0 = blockIdx.x * 128;
    const int qb = wid * 16;

    const __nv_bfloat16* khb = g_kh + (size_t)b * CN;
    const __nv_bfloat16* klb = g_kl + (size_t)b * CN;
    const __nv_bfloat16* vhb = g_vh + (size_t)b * CN;
    const __nv_bfloat16* vlb = g_vl + (size_t)b * CN;

    // per-thread KV load slots: 2 chunks per array (16 rows x 32 chunks = 512)
    const int i0 = tid, i1 = tid + 256;
    const int r0 = i0 >> 5, c0_ = i0 & 31, r1 = i1 >> 5, c1_ = i1 & 31;

    // ---- prologue: Q hi/lo + KV tile 0 (one group) ----
    {
        const __nv_bfloat16* qh = g_qh + (size_t)b * CN + (size_t)m0 * C_;
        const __nv_bfloat16* ql = g_ql + (size_t)b * CN + (size_t)m0 * C_;
#pragma unroll
        for (int it = 0; it < 16; it++) {
            int idx = tid + it * 256;
            int row = idx >> 5, ch = idx & 31;
            cpa16(swz(sb + S_QH, row, ch), qh + idx * 8);
            cpa16(swz(sb + S_QL, row, ch), ql + idx * 8);
        }
        uint32_t st = sb + S_KV;
        cpa16(swz(st + KV_KH, r0, c0_), khb + i0 * 8);
        cpa16(swz(st + KV_KH, r1, c1_), khb + i1 * 8);
        cpa16(swz(st + KV_KL, r0, c0_), klb + i0 * 8);
        cpa16(swz(st + KV_KL, r1, c1_), klb + i1 * 8);
        cpa16(swz(st + KV_VH, r0, c0_), vhb + i0 * 8);
        cpa16(swz(st + KV_VH, r1, c1_), vhb + i1 * 8);
        cpa16(swz(st + KV_VL, r0, c0_), vlb + i0 * 8);
        cpa16(swz(st + KV_VL, r1, c1_), vlb + i1 * 8);
        CP_COMMIT();
    }

    float O_[128];
#pragma unroll
    for (int i = 0; i < 128; i++) O_[i] = 0.f;
    float mA = -CUDART_INF_F, mB = -CUDART_INF_F, lA = 0.f, lB = 0.f;

    // ldmatrix lane address components
    const int rowQ  = qb + (L & 15);
    const int hiA   = L >> 4;
    const int rowK0 = (L & 7) + ((L >> 1) & 8);  // keys 0-15 group
    const int chKs  = (L >> 3) & 1;
    const int rowV  = (L & 15);

    for (int kt = 0; kt < NT; kt++) {
        const uint32_t st = sb + S_KV + (kt & 1) * KV_STRIDE;
        CP_WAIT0();          // tile kt (and Q on kt=0) landed for this thread
        __syncthreads();     // visible to all; all done reading the other stage
        // ---- prefetch tile kt+1 into the other stage (overlaps compute below) ----
        if (kt + 1 < NT) {
            const uint32_t sn = sb + S_KV + ((kt + 1) & 1) * KV_STRIDE;
            const size_t off = (size_t)(kt + 1) * 16 * C_;
            cpa16(swz(sn + KV_KH, r0, c0_), khb + off + i0 * 8);
            cpa16(swz(sn + KV_KH, r1, c1_), khb + off + i1 * 8);
            cpa16(swz(sn + KV_KL, r0, c0_), klb + off + i0 * 8);
            cpa16(swz(sn + KV_KL, r1, c1_), klb + off + i1 * 8);
            cpa16(swz(sn + KV_VH, r0, c0_), vhb + off + i0 * 8);
            cpa16(swz(sn + KV_VH, r1, c1_), vhb + off + i1 * 8);
            cpa16(swz(sn + KV_VL, r0, c0_), vlb + off + i0 * 8);
            cpa16(swz(sn + KV_VL, r1, c1_), vlb + off + i1 * 8);
        }
        CP_COMMIT();

        // ---- S = Qh*Kh + Qh*Kl + Ql*Kh : 6 independent accumulator chains,
        //      2-deep ldmatrix pipeline ----
        float hh0[4] = {0,0,0,0}, hh1[4] = {0,0,0,0};
        float hl0[4] = {0,0,0,0}, hl1[4] = {0,0,0,0};
        float lh0[4] = {0,0,0,0}, lh1[4] = {0,0,0,0};
        uint32_t ah[2][4], al[2][4], kh_[2][4], kl_[2][4];
        ldsm4(ah[0],  swz(sb + S_QH, rowQ, hiA));
        ldsm4(al[0],  swz(sb + S_QL, rowQ, hiA));
        ldsm4(kh_[0], swz(st + KV_KH, rowK0, chKs));
        ldsm4(kl_[0], swz(st + KV_KL, rowK0, chKs));
#pragma unroll
        for (int kc = 0; kc < 16; kc++) {
            const int cur = kc & 1, nxt = cur ^ 1;
            if (kc < 15) {
                int chA = 2 * (kc + 1) + hiA;
                int chB = 2 * (kc + 1) + chKs;
                ldsm4(ah[nxt],  swz(sb + S_QH, rowQ, chA));
                ldsm4(al[nxt],  swz(sb + S_QL, rowQ, chA));
                ldsm4(kh_[nxt], swz(st + KV_KH, rowK0, chB));
                ldsm4(kl_[nxt], swz(st + KV_KL, rowK0, chB));
            }
            mma16816(hh0, ah[cur], kh_[cur]);   mma16816(hh1, ah[cur], kh_[cur] + 2);
            mma16816(hl0, ah[cur], kl_[cur]);   mma16816(hl1, ah[cur], kl_[cur] + 2);
            mma16816(lh0, al[cur], kh_[cur]);   mma16816(lh1, al[cur], kh_[cur] + 2);
        }
        float sacc[2][4];
#pragma unroll
        for (int e = 0; e < 4; e++) {
            sacc[0][e] = hh0[e] + hl0[e] + lh0[e];
            sacc[1][e] = hh1[e] + hl1[e] + lh1[e];
        }

        // ---- online softmax (warp-local; rows rA=L>>2, rB=rA+8) ----
        float tmA = fmaxf(fmaxf(sacc[0][0], sacc[0][1]), fmaxf(sacc[1][0], sacc[1][1]));
        float tmB = fmaxf(fmaxf(sacc[0][2], sacc[0][3]), fmaxf(sacc[1][2], sacc[1][3]));
        tmA = fmaxf(tmA, __shfl_xor_sync(0xffffffffu, tmA, 1));
        tmA = fmaxf(tmA, __shfl_xor_sync(0xffffffffu, tmA, 2));
        tmB = fmaxf(tmB, __shfl_xor_sync(0xffffffffu, tmB, 1));
        tmB = fmaxf(tmB, __shfl_xor_sync(0xffffffffu, tmB, 2));
        float nmA = fmaxf(mA, tmA), nmB = fmaxf(mB, tmB);
        float facA = __expf(mA - nmA), facB = __expf(mB - nmB);
        mA = nmA; mB = nmB;

        uint32_t ph[4], pl[4];
        float sumA = 0.f, sumB = 0.f;
#pragma unroll
        for (int t = 0; t < 2; t++) {
            float p0 = __expf(sacc[t][0] - nmA), p1 = __expf(sacc[t][1] - nmA);
            float p2 = __expf(sacc[t][2] - nmB), p3 = __expf(sacc[t][3] - nmB);
            sumA += p0 + p1; sumB += p2 + p3;
            __nv_bfloat16 h0 = __float2bfloat16(p0), h1 = __float2bfloat16(p1);
            __nv_bfloat16 h2 = __float2bfloat16(p2), h3 = __float2bfloat16(p3);
            ph[2*t]   = pack2(h0, h1);
            ph[2*t+1] = pack2(h2, h3);
            pl[2*t]   = pack2(__float2bfloat16(p0 - __bfloat162float(h0)),
                              __float2bfloat16(p1 - __bfloat162float(h1)));
            pl[2*t+1] = pack2(__float2bfloat16(p2 - __bfloat162float(h2)),
                              __float2bfloat16(p3 - __bfloat162float(h3)));
        }
        sumA += __shfl_xor_sync(0xffffffffu, sumA, 1);
        sumA += __shfl_xor_sync(0xffffffffu, sumA, 2);
        sumB += __shfl_xor_sync(0xffffffffu, sumB, 1);
        sumB += __shfl_xor_sync(0xffffffffu, sumB, 2);
        lA = lA * facA + sumA;
        lB = lB * facB + sumB;

        // rescale O only when a running max actually moved
        if (facA < 1.f || facB < 1.f) {
#pragma unroll
            for (int t = 0; t < 32; t++) {
                O_[4*t+0] *= facA; O_[4*t+1] *= facA;
                O_[4*t+2] *= facB; O_[4*t+3] *= facB;
            }
        }

        // ---- O += Ph*Vh + Ph*Vl + Pl*Vh  (k=16 keys, n=256 ch), 2-deep ldsm pipe ----
        uint32_t vh_[2][4], vl_[2][4];
        ldsm4t(vh_[0], swz(st + KV_VH, rowV, hiA));
        ldsm4t(vl_[0], swz(st + KV_VL, rowV, hiA));
#pragma unroll
        for (int ng = 0; ng < 16; ng++) {
            const int cur = ng & 1, nxt = cur ^ 1;
            if (ng < 15) {
                int cV = 2 * (ng + 1) + hiA;
                ldsm4t(vh_[nxt], swz(st + KV_VH, rowV, cV));
                ldsm4t(vl_[nxt], swz(st + KV_VL, rowV, cV));
            }
            float* o0 = O_ + (2 * ng) * 4;
            float* o1 = O_ + (2 * ng + 1) * 4;
            mma16816(o0, ph, vh_[cur]);   mma16816(o1, ph, vh_[cur] + 2);
            mma16816(o0, ph, vl_[cur]);   mma16816(o1, ph, vl_[cur] + 2);
            mma16816(o0, pl, vh_[cur]);   mma16816(o1, pl, vh_[cur] + 2);
        }
    }

    // ---- epilogue: normalize, stage Os[c][m] (stride 132), fused residual ----
    __syncthreads();
    {
        float* Os = (float*)sm;
        float invA = 1.f / lA, invB = 1.f / lB;
        int mAi = qb + (L >> 2), mBi = mAi + 8;
        int cb = (L & 3) * 2;
#pragma unroll
        for (int t = 0; t < 32; t++) {
            int c = t * 8 + cb;
            Os[c * 132 + mAi]       = O_[4*t+0] * invA;
            Os[(c + 1) * 132 + mAi] = O_[4*t+1] * invA;
            Os[c * 132 + mBi]       = O_[4*t+2] * invB;
            Os[(c + 1) * 132 + mBi] = O_[4*t+3] * invB;
        }
    }
    __syncthreads();
    {
        const float gm = gamma[0];
        const float* Os = (const float*)sm;
        const float* xb = x + (size_t)b * CN;
        float* ob = out + (size_t)b * CN;
        for (int idx = tid; idx < 32768; idx += 256) {
            int c = idx >> 7, m = idx & 127;
            size_t g = (size_t)c * N_ + m0 + m;
            ob[g] = gm * Os[c * 132 + m] + xb[g];
        }
    }
}

extern "C" void kernel_launch(void* const* d_in, const int* in_sizes, int n_in,
                              void* d_out, int out_size)
{
    const float* x     = (const float*)d_in[0];
    const float* Wq    = (const float*)d_in[1];
    const float* bq    = (const float*)d_in[2];
    const float* Wk    = (const float*)d_in[3];
    const float* bk    = (const float*)d_in[4];
    const float* Wv    = (const float*)d_in[5];
    const float* bv    = (const float*)d_in[6];
    const float* rh    = (const float*)d_in[7];
    const float* rw    = (const float*)d_in[8];
    const float* gamma = (const float*)d_in[9];
    float* out = (float*)d_out;

    dim3 gp(N_ / 64, C_ / 64, B_ * 3);
    proj_kernel<<<gp, 256>>>(x, Wq, bq, Wk, bk, Wv, bv, rh, rw);

    cudaFuncSetAttribute(attn_kernel, cudaFuncAttributeMaxDynamicSharedMemorySize, SMEM_SZ);
    dim3 ga(N_ / 128, B_);
    attn_kernel<<<ga, 256, SMEM_SZ>>>(x, gamma, out);
}

// round 16
// speedup vs baseline: 3.9237x; 1.2111x over previous
#include <cuda_runtime.h>
#include <cuda_bf16.h>
#include <math_constants.h>
#include <cstdint>

#define B_ 4
#define C_ 256
#define N_ 4096
#define CN (C_*N_)

// bf16 hi/lo operands, all in [b][n][c] row-major (c contiguous)
static __device__ __align__(16) __nv_bfloat16 g_qh[B_*CN], g_ql[B_*CN];
static __device__ __align__(16) __nv_bfloat16 g_kh[B_*CN], g_kl[B_*CN];
static __device__ __align__(16) __nv_bfloat16 g_vh[B_*CN], g_vl[B_*CN];
// pre-converted inputs for tensorized proj
static __device__ __align__(16) __nv_bfloat16 g_xh[B_*CN], g_xl[B_*CN];
static __device__ __align__(16) __nv_bfloat16 g_wh[3*C_*C_], g_wl[3*C_*C_];

// ---------------------------------------------------------------------------
// helpers (sm_80-level PTX only: cp.async, ldmatrix, mma.sync bf16)
// ---------------------------------------------------------------------------
__device__ __forceinline__ uint32_t smem_u32(const void* p){
    uint32_t a;
    asm("{ .reg .u64 t; cvta.to.shared.u64 t, %1; cvt.u32.u64 %0, t; }" : "=r"(a) : "l"(p));
    return a;
}
__device__ __forceinline__ void cpa16(uint32_t dst, const void* src){
    asm volatile("cp.async.cg.shared.global [%0], [%1], 16;" :: "r"(dst), "l"(src));
}
#define CP_COMMIT() asm volatile("cp.async.commit_group;" ::: "memory")
#define CP_WAIT0()  asm volatile("cp.async.wait_group 0;" ::: "memory")

__device__ __forceinline__ void ldsm4(uint32_t* r, uint32_t a){
    asm volatile("ldmatrix.sync.aligned.m8n8.x4.shared.b16 {%0,%1,%2,%3}, [%4];"
        : "=r"(r[0]),"=r"(r[1]),"=r"(r[2]),"=r"(r[3]) : "r"(a));
}
__device__ __forceinline__ void ldsm4t(uint32_t* r, uint32_t a){
    asm volatile("ldmatrix.sync.aligned.m8n8.x4.trans.shared.b16 {%0,%1,%2,%3}, [%4];"
        : "=r"(r[0]),"=r"(r[1]),"=r"(r[2]),"=r"(r[3]) : "r"(a));
}
__device__ __forceinline__ void mma16816(float* d, const uint32_t* a, const uint32_t* b){
    asm volatile("mma.sync.aligned.m16n8k16.row.col.f32.bf16.bf16.f32 "
        "{%0,%1,%2,%3}, {%4,%5,%6,%7}, {%8,%9}, {%0,%1,%2,%3};"
        : "+f"(d[0]),"+f"(d[1]),"+f"(d[2]),"+f"(d[3])
        : "r"(a[0]),"r"(a[1]),"r"(a[2]),"r"(a[3]),"r"(b[0]),"r"(b[1]));
}
__device__ __forceinline__ uint32_t pack2(__nv_bfloat16 a, __nv_bfloat16 b){
    uint32_t lo = *reinterpret_cast<uint16_t*>(&a);
    uint32_t hi = *reinterpret_cast<uint16_t*>(&b);
    return lo | (hi << 16);
}
__device__ __forceinline__ uint32_t split_hi(float a, float b, uint32_t& lo_out){
    __nv_bfloat16 ha = __float2bfloat16(a), hb = __float2bfloat16(b);
    lo_out = pack2(__float2bfloat16(a - __bfloat162float(ha)),
                   __float2bfloat16(b - __bfloat162float(hb)));
    return pack2(ha, hb);
}
// XOR swizzle: rows of 512B (32 x 16B chunks); conflict-free ldmatrix
__device__ __forceinline__ uint32_t swz(uint32_t base, int row, int chunk){
    return base + row * 512 + (((chunk ^ row) & 7) << 4) + ((chunk & 24) << 4);
}

// ---------------------------------------------------------------------------
// W pre-convert: fp32 [3][o][c] -> bf16 hi/lo.  grid 192 x 256.
// ---------------------------------------------------------------------------
__global__ void wconv_kernel(const float* __restrict__ Wq,
                             const float* __restrict__ Wk,
                             const float* __restrict__ Wv)
{
    int idx = blockIdx.x * 256 + threadIdx.x;     // float4 index, 0..49151
    int p = idx >> 14, r = idx & 16383;
    const float* W = (p == 0) ? Wq : ((p == 1) ? Wk : Wv);
    float4 v = ((const float4*)W)[r];
    uint32_t l0, l1;
    uint32_t h0 = split_hi(v.x, v.y, l0);
    uint32_t h1 = split_hi(v.z, v.w, l1);
    ((uint2*)(g_wh + p * C_ * C_))[r] = make_uint2(h0, h1);
    ((uint2*)(g_wl + p * C_ * C_))[r] = make_uint2(l0, l1);
}

// ---------------------------------------------------------------------------
// x pre-convert: fp32 [b][c][n] -> bf16 hi/lo [b][n][c].  grid (64,4,4) x 256.
// ---------------------------------------------------------------------------
__global__ void xconv_kernel(const float* __restrict__ x)
{
    __shared__ float Xs[64][68];
    const int tid = threadIdx.x;
    const int n0 = blockIdx.x * 64, c0 = blockIdx.y * 64, b = blockIdx.z;
    const float* xb = x + (size_t)b * CN;
#pragma unroll
    for (int it = 0; it < 4; it++) {
        int idx = it * 256 + tid;
        int c = idx >> 4, q = idx & 15;
        float4 v = *(const float4*)&xb[(size_t)(c0 + c) * N_ + n0 + 4 * q];
        *(float4*)&Xs[c][4 * q] = v;
    }
    __syncthreads();
#pragma unroll
    for (int it = 0; it < 8; it++) {
        int o = it * 256 + tid;
        int n = o >> 5, cp = o & 31;
        float a = Xs[2 * cp][n], bb = Xs[2 * cp + 1][n];
        uint32_t lo;
        uint32_t hi = split_hi(a, bb, lo);
        ((uint32_t*)(g_xh + (size_t)b * CN + (size_t)(n0 + n) * C_ + c0))[cp] = hi;
        ((uint32_t*)(g_xl + (size_t)b * CN + (size_t)(n0 + n) * C_ + c0))[cp] = lo;
    }
}

// ---------------------------------------------------------------------------
// Tensorized projection: HMMA hi/lo GEMM.  grid (32, 4), 256 threads.
// SMEM: XH 0..64K, XL 64..128K (128 pixels x 512B, swizzled — same as attn Q),
//       WH 128K..160K, WL 160K..192K (64 outs x 512B, one chunk).
// 12 chunks = {q,k,v} x 4 out-64 groups.  3-term MMA: xh*wh + xh*wl + xl*wh.
// ---------------------------------------------------------------------------
#define P_XH 0
#define P_XL 65536
#define P_WH 131072
#define P_WL 163840
#define SMEM_SZ 196608

__global__ __launch_bounds__(256, 1)
void proj_kernel(const float* __restrict__ bq, const float* __restrict__ bk,
                 const float* __restrict__ bv,
                 const float* __restrict__ rh, const float* __restrict__ rw)
{
    extern __shared__ __align__(1024) char sm[];
    const uint32_t sb = smem_u32(sm);
    const int tid = threadIdx.x;
    const int wid = tid >> 5, L = tid & 31;
    const int b = blockIdx.y, n0 = blockIdx.x * 128;
    const int qb = wid * 16;

    // ---- stage X hi/lo (once) + W chunk 0 ----
    {
        const __nv_bfloat16* xh = g_xh + (size_t)b * CN + (size_t)n0 * C_;
        const __nv_bfloat16* xl = g_xl + (size_t)b * CN + (size_t)n0 * C_;
#pragma unroll
        for (int it = 0; it < 16; it++) {
            int idx = tid + it * 256;
            int row = idx >> 5, ch = idx & 31;
            cpa16(swz(sb + P_XH, row, ch), xh + idx * 8);
            cpa16(swz(sb + P_XL, row, ch), xl + idx * 8);
        }
#pragma unroll
        for (int it = 0; it < 8; it++) {
            int idx = tid + it * 256;
            int row = idx >> 5, ch = idx & 31;
            cpa16(swz(sb + P_WH, row, ch), g_wh + idx * 8);
            cpa16(swz(sb + P_WL, row, ch), g_wl + idx * 8);
        }
        CP_COMMIT(); CP_WAIT0();
        __syncthreads();
    }

    // fragment lane addressing (identical to attn S-GEMM)
    const int rowX  = qb + (L & 15);
    const int hiA   = L >> 4;
    const int rowK0 = (L & 7) + ((L >> 1) & 8);
    const int chKs  = (L >> 3) & 1;

    for (int pc = 0; pc < 12; pc++) {
        const int p = pc >> 2, oc = pc & 3;

        float acc[4][8];
#pragma unroll
        for (int g = 0; g < 4; g++)
#pragma unroll
            for (int e = 0; e < 8; e++) acc[g][e] = 0.f;

#pragma unroll 4
        for (int kc = 0; kc < 16; kc++) {
            uint32_t ah[4], al[4];
            int chA = 2 * kc + hiA;
            int chB = 2 * kc + chKs;
            ldsm4(ah, swz(sb + P_XH, rowX, chA));
            ldsm4(al, swz(sb + P_XL, rowX, chA));
#pragma unroll
            for (int g = 0; g < 4; g++) {
                uint32_t bh[4], bl[4];
                ldsm4(bh, swz(sb + P_WH, g * 16 + rowK0, chB));
                ldsm4(bl, swz(sb + P_WL, g * 16 + rowK0, chB));
                mma16816(acc[g],     ah, bh);   mma16816(acc[g] + 4, ah, bh + 2);
                mma16816(acc[g],     ah, bl);   mma16816(acc[g] + 4, ah, bl + 2);
                mma16816(acc[g],     al, bh);   mma16816(acc[g] + 4, al, bh + 2);
            }
        }

        // ---- epilogue: bias (+pos for k), hi/lo split, store [n][c] ----
        {
            const float* bias = (p == 0) ? bq : ((p == 1) ? bk : bv);
            __nv_bfloat16* oH = ((p == 0) ? g_qh : ((p == 1) ? g_kh : g_vh)) + (size_t)b * CN;
            __nv_bfloat16* oL = ((p == 0) ? g_ql : ((p == 1) ? g_kl : g_vl)) + (size_t)b * CN;
            const int nA = n0 + qb + (L >> 2), nB = nA + 8;
#pragma unroll
            for (int g = 0; g < 4; g++)
#pragma unroll
                for (int s = 0; s < 2; s++) {
                    int c = oc * 64 + g * 16 + s * 8 + (L & 3) * 2;
                    float b0 = bias[c], b1 = bias[c + 1];
                    float vA0 = acc[g][4 * s + 0] + b0, vA1 = acc[g][4 * s + 1] + b1;
                    float vB0 = acc[g][4 * s + 2] + b0, vB1 = acc[g][4 * s + 3] + b1;
                    if (p == 1) {
                        float rh0 = rh[c * 64 + (nA >> 6)], rh0b = rh[c * 64 + (nB >> 6)];
                        float rh1 = rh[(c + 1) * 64 + (nA >> 6)], rh1b = rh[(c + 1) * 64 + (nB >> 6)];
                        vA0 += rh0  + rw[c * 64 + (nA & 63)];
                        vA1 += rh1  + rw[(c + 1) * 64 + (nA & 63)];
                        vB0 += rh0b + rw[c * 64 + (nB & 63)];
                        vB1 += rh1b + rw[(c + 1) * 64 + (nB & 63)];
                    }
                    uint32_t loA, loB;
                    uint32_t hiA_ = split_hi(vA0, vA1, loA);
                    uint32_t hiB_ = split_hi(vB0, vB1, loB);
                    ((uint32_t*)(oH + (size_t)nA * C_ + c))[0] = hiA_;
                    ((uint32_t*)(oL + (size_t)nA * C_ + c))[0] = loA;
                    ((uint32_t*)(oH + (size_t)nB * C_ + c))[0] = hiB_;
                    ((uint32_t*)(oL + (size_t)nB * C_ + c))[0] = loB;
                }
        }

        // ---- stage next W chunk ----
        if (pc < 11) {
            __syncthreads();
            const int pn = (pc + 1) >> 2, on = (pc + 1) & 3;
            const __nv_bfloat16* wh = g_wh + pn * C_ * C_ + on * 64 * C_;
            const __nv_bfloat16* wl = g_wl + pn * C_ * C_ + on * 64 * C_;
#pragma unroll
            for (int it = 0; it < 8; it++) {
                int idx = tid + it * 256;
                int row = idx >> 5, ch = idx & 31;
                cpa16(swz(sb + P_WH, row, ch), wh + idx * 8);
                cpa16(swz(sb + P_WL, row, ch), wl + idx * 8);
            }
            CP_COMMIT(); CP_WAIT0();
            __syncthreads();
        }
    }
}

// ---------------------------------------------------------------------------
// mma.sync flash-attention (unchanged from R15 WIN).
// ---------------------------------------------------------------------------
#define S_QH 0
#define S_QL 65536
#define S_KV 131072
#define KV_STRIDE 32768
#define KV_KH 0
#define KV_KL 8192
#define KV_VH 16384
#define KV_VL 24576
#define NT 256           /* 4096 keys / 16 */

__global__ __launch_bounds__(256, 1)
void attn_kernel(const float* __restrict__ x,
                 const float* __restrict__ gamma,
                 float* __restrict__ out)
{
    extern __shared__ __align__(1024) char sm[];
    const uint32_t sb = smem_u32(sm);
    const int tid = threadIdx.x;
    const int wid = tid >> 5, L = tid & 31;
    const int b = blockIdx.y, m0 = blockIdx.x * 128;
    const int qb = wid * 16;

    const __nv_bfloat16* khb = g_kh + (size_t)b * CN;
    const __nv_bfloat16* klb = g_kl + (size_t)b * CN;
    const __nv_bfloat16* vhb = g_vh + (size_t)b * CN;
    const __nv_bfloat16* vlb = g_vl + (size_t)b * CN;

    const int i0 = tid, i1 = tid + 256;
    const int r0 = i0 >> 5, c0_ = i0 & 31, r1 = i1 >> 5, c1_ = i1 & 31;

    {
        const __nv_bfloat16* qh = g_qh + (size_t)b * CN + (size_t)m0 * C_;
        const __nv_bfloat16* ql = g_ql + (size_t)b * CN + (size_t)m0 * C_;
#pragma unroll
        for (int it = 0; it < 16; it++) {
            int idx = tid + it * 256;
            int row = idx >> 5, ch = idx & 31;
            cpa16(swz(sb + S_QH, row, ch), qh + idx * 8);
            cpa16(swz(sb + S_QL, row, ch), ql + idx * 8);
        }
        uint32_t st = sb + S_KV;
        cpa16(swz(st + KV_KH, r0, c0_), khb + i0 * 8);
        cpa16(swz(st + KV_KH, r1, c1_), khb + i1 * 8);
        cpa16(swz(st + KV_KL, r0, c0_), klb + i0 * 8);
        cpa16(swz(st + KV_KL, r1, c1_), klb + i1 * 8);
        cpa16(swz(st + KV_VH, r0, c0_), vhb + i0 * 8);
        cpa16(swz(st + KV_VH, r1, c1_), vhb + i1 * 8);
        cpa16(swz(st + KV_VL, r0, c0_), vlb + i0 * 8);
        cpa16(swz(st + KV_VL, r1, c1_), vlb + i1 * 8);
        CP_COMMIT();
    }

    float O_[128];
#pragma unroll
    for (int i = 0; i < 128; i++) O_[i] = 0.f;
    float mA = -CUDART_INF_F, mB = -CUDART_INF_F, lA = 0.f, lB = 0.f;

    const int rowQ  = qb + (L & 15);
    const int hiA   = L >> 4;
    const int rowK0 = (L & 7) + ((L >> 1) & 8);
    const int chKs  = (L >> 3) & 1;
    const int rowV  = (L & 15);

    for (int kt = 0; kt < NT; kt++) {
        const uint32_t st = sb + S_KV + (kt & 1) * KV_STRIDE;
        CP_WAIT0();
        __syncthreads();
        if (kt + 1 < NT) {
            const uint32_t sn = sb + S_KV + ((kt + 1) & 1) * KV_STRIDE;
            const size_t off = (size_t)(kt + 1) * 16 * C_;
            cpa16(swz(sn + KV_KH, r0, c0_), khb + off + i0 * 8);
            cpa16(swz(sn + KV_KH, r1, c1_), khb + off + i1 * 8);
            cpa16(swz(sn + KV_KL, r0, c0_), klb + off + i0 * 8);
            cpa16(swz(sn + KV_KL, r1, c1_), klb + off + i1 * 8);
            cpa16(swz(sn + KV_VH, r0, c0_), vhb + off + i0 * 8);
            cpa16(swz(sn + KV_VH, r1, c1_), vhb + off + i1 * 8);
            cpa16(swz(sn + KV_VL, r0, c0_), vlb + off + i0 * 8);
            cpa16(swz(sn + KV_VL, r1, c1_), vlb + off + i1 * 8);
        }
        CP_COMMIT();

        float hh0[4] = {0,0,0,0}, hh1[4] = {0,0,0,0};
        float hl0[4] = {0,0,0,0}, hl1[4] = {0,0,0,0};
        float lh0[4] = {0,0,0,0}, lh1[4] = {0,0,0,0};
        uint32_t ah[2][4], al[2][4], kh_[2][4], kl_[2][4];
        ldsm4(ah[0],  swz(sb + S_QH, rowQ, hiA));
        ldsm4(al[0],  swz(sb + S_QL, rowQ, hiA));
        ldsm4(kh_[0], swz(st + KV_KH, rowK0, chKs));
        ldsm4(kl_[0], swz(st + KV_KL, rowK0, chKs));
#pragma unroll
        for (int kc = 0; kc < 16; kc++) {
            const int cur = kc & 1, nxt = cur ^ 1;
            if (kc < 15) {
                int chA = 2 * (kc + 1) + hiA;
                int chB = 2 * (kc + 1) + chKs;
                ldsm4(ah[nxt],  swz(sb + S_QH, rowQ, chA));
                ldsm4(al[nxt],  swz(sb + S_QL, rowQ, chA));
                ldsm4(kh_[nxt], swz(st + KV_KH, rowK0, chB));
                ldsm4(kl_[nxt], swz(st + KV_KL, rowK0, chB));
            }
            mma16816(hh0, ah[cur], kh_[cur]);   mma16816(hh1, ah[cur], kh_[cur] + 2);
            mma16816(hl0, ah[cur], kl_[cur]);   mma16816(hl1, ah[cur], kl_[cur] + 2);
            mma16816(lh0, al[cur], kh_[cur]);   mma16816(lh1, al[cur], kh_[cur] + 2);
        }
        float sacc[2][4];
#pragma unroll
        for (int e = 0; e < 4; e++) {
            sacc[0][e] = hh0[e] + hl0[e] + lh0[e];
            sacc[1][e] = hh1[e] + hl1[e] + lh1[e];
        }

        float tmA = fmaxf(fmaxf(sacc[0][0], sacc[0][1]), fmaxf(sacc[1][0], sacc[1][1]));
        float tmB = fmaxf(fmaxf(sacc[0][2], sacc[0][3]), fmaxf(sacc[1][2], sacc[1][3]));
        tmA = fmaxf(tmA, __shfl_xor_sync(0xffffffffu, tmA, 1));
        tmA = fmaxf(tmA, __shfl_xor_sync(0xffffffffu, tmA, 2));
        tmB = fmaxf(tmB, __shfl_xor_sync(0xffffffffu, tmB, 1));
        tmB = fmaxf(tmB, __shfl_xor_sync(0xffffffffu, tmB, 2));
        float nmA = fmaxf(mA, tmA), nmB = fmaxf(mB, tmB);
        float facA = __expf(mA - nmA), facB = __expf(mB - nmB);
        mA = nmA; mB = nmB;

        uint32_t ph[4], pl[4];
        float sumA = 0.f, sumB = 0.f;
#pragma unroll
        for (int t = 0; t < 2; t++) {
            float p0 = __expf(sacc[t][0] - nmA), p1 = __expf(sacc[t][1] - nmA);
            float p2 = __expf(sacc[t][2] - nmB), p3 = __expf(sacc[t][3] - nmB);
            sumA += p0 + p1; sumB += p2 + p3;
            __nv_bfloat16 h0 = __float2bfloat16(p0), h1 = __float2bfloat16(p1);
            __nv_bfloat16 h2 = __float2bfloat16(p2), h3 = __float2bfloat16(p3);
            ph[2*t]   = pack2(h0, h1);
            ph[2*t+1] = pack2(h2, h3);
            pl[2*t]   = pack2(__float2bfloat16(p0 - __bfloat162float(h0)),
                              __float2bfloat16(p1 - __bfloat162float(h1)));
            pl[2*t+1] = pack2(__float2bfloat16(p2 - __bfloat162float(h2)),
                              __float2bfloat16(p3 - __bfloat162float(h3)));
        }
        sumA += __shfl_xor_sync(0xffffffffu, sumA, 1);
        sumA += __shfl_xor_sync(0xffffffffu, sumA, 2);
        sumB += __shfl_xor_sync(0xffffffffu, sumB, 1);
        sumB += __shfl_xor_sync(0xffffffffu, sumB, 2);
        lA = lA * facA + sumA;
        lB = lB * facB + sumB;

        if (facA < 1.f || facB < 1.f) {
#pragma unroll
            for (int t = 0; t < 32; t++) {
                O_[4*t+0] *= facA; O_[4*t+1] *= facA;
                O_[4*t+2] *= facB; O_[4*t+3] *= facB;
            }
        }

        uint32_t vh_[2][4], vl_[2][4];
        ldsm4t(vh_[0], swz(st + KV_VH, rowV, hiA));
        ldsm4t(vl_[0], swz(st + KV_VL, rowV, hiA));
#pragma unroll
        for (int ng = 0; ng < 16; ng++) {
            const int cur = ng & 1, nxt = cur ^ 1;
            if (ng < 15) {
                int cV = 2 * (ng + 1) + hiA;
                ldsm4t(vh_[nxt], swz(st + KV_VH, rowV, cV));
                ldsm4t(vl_[nxt], swz(st + KV_VL, rowV, cV));
            }
            float* o0 = O_ + (2 * ng) * 4;
            float* o1 = O_ + (2 * ng + 1) * 4;
            mma16816(o0, ph, vh_[cur]);   mma16816(o1, ph, vh_[cur] + 2);
            mma16816(o0, ph, vl_[cur]);   mma16816(o1, ph, vl_[cur] + 2);
            mma16816(o0, pl, vh_[cur]);   mma16816(o1, pl, vh_[cur] + 2);
        }
    }

    __syncthreads();
    {
        float* Os = (float*)sm;
        float invA = 1.f / lA, invB = 1.f / lB;
        int mAi = qb + (L >> 2), mBi = mAi + 8;
        int cb = (L & 3) * 2;
#pragma unroll
        for (int t = 0; t < 32; t++) {
            int c = t * 8 + cb;
            Os[c * 132 + mAi]       = O_[4*t+0] * invA;
            Os[(c + 1) * 132 + mAi] = O_[4*t+1] * invA;
            Os[c * 132 + mBi]       = O_[4*t+2] * invB;
            Os[(c + 1) * 132 + mBi] = O_[4*t+3] * invB;
        }
    }
    __syncthreads();
    {
        const float gm = gamma[0];
        const float* Os = (const float*)sm;
        const float* xb = x + (size_t)b * CN;
        float* ob = out + (size_t)b * CN;
        for (int idx = tid; idx < 32768; idx += 256) {
            int c = idx >> 7, m = idx & 127;
            size_t g = (size_t)c * N_ + m0 + m;
            ob[g] = gm * Os[c * 132 + m] + xb[g];
        }
    }
}

extern "C" void kernel_launch(void* const* d_in, const int* in_sizes, int n_in,
                              void* d_out, int out_size)
{
    const float* x     = (const float*)d_in[0];
    const float* Wq    = (const float*)d_in[1];
    const float* bq    = (const float*)d_in[2];
    const float* Wk    = (const float*)d_in[3];
    const float* bk    = (const float*)d_in[4];
    const float* Wv    = (const float*)d_in[5];
    const float* bv    = (const float*)d_in[6];
    const float* rh    = (const float*)d_in[7];
    const float* rw    = (const float*)d_in[8];
    const float* gamma = (const float*)d_in[9];
    float* out = (float*)d_out;

    wconv_kernel<<<192, 256>>>(Wq, Wk, Wv);
    dim3 gx(N_ / 64, C_ / 64, B_);
    xconv_kernel<<<gx, 256>>>(x);

    cudaFuncSetAttribute(proj_kernel, cudaFuncAttributeMaxDynamicSharedMemorySize, SMEM_SZ);
    dim3 gp(N_ / 128, B_);
    proj_kernel<<<gp, 256, SMEM_SZ>>>(bq, bk, bv, rh, rw);

    cudaFuncSetAttribute(attn_kernel, cudaFuncAttributeMaxDynamicSharedMemorySize, SMEM_SZ);
    dim3 ga(N_ / 128, B_);
    attn_kernel<<<ga, 256, SMEM_SZ>>>(x, gamma, out);
}